// round 13
// baseline (speedup 1.0000x reference)
#include <cuda_runtime.h>
#include <cuda_bf16.h>
#include <math.h>
#include <stdint.h>

#define Bv 4
#define Sv 2048
#define Dv 1024
#define Hv 16
#define HDv 64
#define Mv (Bv * Sv)          // 8192
#define EPSv 1e-7f

// ---------------- scratch (static device memory; no allocs) ----------------
__device__ __nv_bfloat16 g_xhi[Mv * Dv], g_xlo[Mv * Dv];
__device__ __nv_bfloat16 g_wh[4][Dv * Dv], g_wl[4][Dv * Dv];  // transposed [N][K]
__device__ __nv_bfloat16 g_qhi[Mv * Dv], g_qlo[Mv * Dv];
__device__ __nv_bfloat16 g_khi[Mv * Dv], g_klo[Mv * Dv];
__device__ __nv_bfloat16 g_vhi[Mv * Dv], g_vlo[Mv * Dv];
__device__ __nv_bfloat16 g_chi[Mv * Dv], g_clo[Mv * Dv];

struct ProjOut {
    const float* bias[3];
    __nv_bfloat16* oh[3];
    __nv_bfloat16* ol[3];
};
struct WSrc { const float* w[4]; };

// ======================= helpers ===========================================
__device__ __forceinline__ uint32_t smem_u32(const void* p) {
    uint32_t a;
    asm("{ .reg .u64 t; cvta.to.shared.u64 t, %1; cvt.u32.u64 %0, t; }"
        : "=r"(a) : "l"(p));
    return a;
}

__device__ __forceinline__ void cpa16(uint32_t d, const void* g) {
    asm volatile("cp.async.cg.shared.global [%0], [%1], 16;" :: "r"(d), "l"(g));
}
#define CP_COMMIT() asm volatile("cp.async.commit_group;" ::: "memory")
#define CP_WAIT0()  asm volatile("cp.async.wait_group 0;" ::: "memory")
#define CP_WAIT1()  asm volatile("cp.async.wait_group 1;" ::: "memory")

__device__ __forceinline__ void ldsm4(uint32_t* r, uint32_t a) {
    asm volatile("ldmatrix.sync.aligned.m8n8.x4.shared.b16 {%0,%1,%2,%3}, [%4];"
        : "=r"(r[0]), "=r"(r[1]), "=r"(r[2]), "=r"(r[3]) : "r"(a));
}
__device__ __forceinline__ void ldsm4t(uint32_t* r, uint32_t a) {
    asm volatile("ldmatrix.sync.aligned.m8n8.x4.trans.shared.b16 {%0,%1,%2,%3}, [%4];"
        : "=r"(r[0]), "=r"(r[1]), "=r"(r[2]), "=r"(r[3]) : "r"(a));
}

__device__ __forceinline__ void mma_bf16(float* d, const uint32_t* a, const uint32_t* b) {
    asm volatile(
        "mma.sync.aligned.m16n8k16.row.col.f32.bf16.bf16.f32 "
        "{%0,%1,%2,%3}, {%4,%5,%6,%7}, {%8,%9}, {%0,%1,%2,%3};"
        : "+f"(d[0]), "+f"(d[1]), "+f"(d[2]), "+f"(d[3])
        : "r"(a[0]), "r"(a[1]), "r"(a[2]), "r"(a[3]), "r"(b[0]), "r"(b[1]));
}

__device__ __forceinline__ uint32_t packf_hi(float a, float b) {
    __nv_bfloat162 t;
    t.x = __float2bfloat16(a); t.y = __float2bfloat16(b);
    return *reinterpret_cast<uint32_t*>(&t);
}
__device__ __forceinline__ uint32_t packf_lo(float a, float b) {
    __nv_bfloat162 t;
    t.x = __float2bfloat16(a - __bfloat162float(__float2bfloat16(a)));
    t.y = __float2bfloat16(b - __bfloat162float(__float2bfloat16(b)));
    return *reinterpret_cast<uint32_t*>(&t);
}

// ---------------- convert kernels ------------------------------------------
__global__ __launch_bounds__(256) void split_rm(
    const float4* __restrict__ src, __nv_bfloat162* __restrict__ hi,
    __nv_bfloat162* __restrict__ lo, int n4)
{
    int i = blockIdx.x * 256 + threadIdx.x;
    if (i >= n4) return;
    float4 v = src[i];
    __nv_bfloat16 h0 = __float2bfloat16(v.x), h1 = __float2bfloat16(v.y);
    __nv_bfloat16 h2 = __float2bfloat16(v.z), h3 = __float2bfloat16(v.w);
    __nv_bfloat162 a; a.x = h0; a.y = h1;
    __nv_bfloat162 b; b.x = h2; b.y = h3;
    hi[2 * i] = a; hi[2 * i + 1] = b;
    a.x = __float2bfloat16(v.x - __bfloat162float(h0));
    a.y = __float2bfloat16(v.y - __bfloat162float(h1));
    b.x = __float2bfloat16(v.z - __bfloat162float(h2));
    b.y = __float2bfloat16(v.w - __bfloat162float(h3));
    lo[2 * i] = a; lo[2 * i + 1] = b;
}

// all 4 weights: [K][N] row-major -> transposed bf16 hi/lo [N][K], grid.z picks W
__global__ __launch_bounds__(256) void tsplit4(
    WSrc ws, __nv_bfloat16* __restrict__ th4, __nv_bfloat16* __restrict__ tl4)
{
    __shared__ float t[32][33];
    const float* W = ws.w[blockIdx.z];
    __nv_bfloat16* th = th4 + (size_t)blockIdx.z * Dv * Dv;
    __nv_bfloat16* tl = tl4 + (size_t)blockIdx.z * Dv * Dv;
    const int n0 = blockIdx.x * 32, k0 = blockIdx.y * 32;
    const int tx = threadIdx.x & 31, ty = threadIdx.x >> 5;
    #pragma unroll
    for (int r = ty; r < 32; r += 8)
        t[r][tx] = W[(size_t)(k0 + r) * Dv + n0 + tx];
    __syncthreads();
    #pragma unroll
    for (int r = ty; r < 32; r += 8) {
        float v = t[tx][r];
        __nv_bfloat16 h = __float2bfloat16(v);
        th[(size_t)(n0 + r) * Dv + k0 + tx] = h;
        tl[(size_t)(n0 + r) * Dv + k0 + tx] = __float2bfloat16(v - __bfloat162float(h));
    }
}

// ================== mma.sync split-bf16 GEMM (R10, unchanged) ===============
#define NIT   32
#define PITCH 80
#define OFF_AH 0
#define OFF_AL 10240
#define OFF_BH 20480
#define OFF_BL 30720
#define STG    40960
#define SMEM_G (2 * STG)

#define GEMM_PROLOGUE_AND_LOOP(Ah_, Al_, Bh_, Bl_)                              \
    float acc[4][8][4];                                                         \
    _Pragma("unroll")                                                           \
    for (int i = 0; i < 4; i++)                                                 \
        _Pragma("unroll")                                                       \
        for (int j = 0; j < 8; j++) {                                           \
            acc[i][j][0] = 0.f; acc[i][j][1] = 0.f;                             \
            acc[i][j][2] = 0.f; acc[i][j][3] = 0.f;                             \
        }                                                                       \
    const int crow[4] = { tid >> 2, (tid + 128) >> 2, (tid + 256) >> 2,         \
                          (tid + 384) >> 2 };                                   \
    const int kc = tid & 3;                                                     \
    uint32_t soX[4]; size_t gaX[4], gbX[4];                                     \
    _Pragma("unroll")                                                           \
    for (int t = 0; t < 4; t++) {                                               \
        soX[t] = (uint32_t)(crow[t] * PITCH + kc * 16);                         \
        gaX[t] = (size_t)(bm + crow[t]) * Dv + kc * 8;                          \
        gbX[t] = (size_t)(bn + crow[t]) * Dv + kc * 8;                          \
    }                                                                           \
    const uint32_t aByte = (uint32_t)((wm * 64 + (lane & 15)) * PITCH           \
                                      + (lane >> 4) * 16);                      \
    const uint32_t bByte = (uint32_t)((wn * 64 + (lane >> 4) * 8 + (lane & 7))  \
                                      * PITCH + ((lane >> 3) & 1) * 16);        \
    {   /* prologue: stage 0 */                                                 \
        const uint32_t s = sb;                                                  \
        _Pragma("unroll")                                                       \
        for (int t = 0; t < 4; t++) {                                           \
            cpa16(s + OFF_AH + soX[t], Ah_ + gaX[t]);                           \
            cpa16(s + OFF_AL + soX[t], Al_ + gaX[t]);                           \
            cpa16(s + OFF_BH + soX[t], Bh_ + gbX[t]);                           \
            cpa16(s + OFF_BL + soX[t], Bl_ + gbX[t]);                           \
        }                                                                       \
        CP_COMMIT();                                                            \
    }                                                                           \
    _Pragma("unroll 1")                                                         \
    for (int it = 0; it < NIT; it++) {                                          \
        CP_WAIT0();                                                             \
        __syncthreads();                                                        \
        if (it + 1 < NIT) {                                                     \
            const int k0 = (it + 1) * 32;                                       \
            const uint32_t s = sb + ((it + 1) & 1) * STG;                       \
            _Pragma("unroll")                                                   \
            for (int t = 0; t < 4; t++) {                                       \
                cpa16(s + OFF_AH + soX[t], Ah_ + gaX[t] + k0);                  \
                cpa16(s + OFF_AL + soX[t], Al_ + gaX[t] + k0);                  \
                cpa16(s + OFF_BH + soX[t], Bh_ + gbX[t] + k0);                  \
                cpa16(s + OFF_BL + soX[t], Bl_ + gbX[t] + k0);                  \
            }                                                                   \
            CP_COMMIT();                                                        \
        }                                                                       \
        const uint32_t aB = sb + (it & 1) * STG + aByte;                        \
        const uint32_t bB = sb + (it & 1) * STG + bByte;                        \
        _Pragma("unroll")                                                       \
        for (int ks = 0; ks < 2; ks++) {                                        \
            uint32_t ahr[4][4], alr[4][4], bhr[4][4], blr[4][4];                \
            _Pragma("unroll")                                                   \
            for (int mt = 0; mt < 4; mt++) {                                    \
                ldsm4(ahr[mt], aB + OFF_AH + mt * (16 * PITCH) + ks * 32);      \
                ldsm4(alr[mt], aB + OFF_AL + mt * (16 * PITCH) + ks * 32);      \
            }                                                                   \
            _Pragma("unroll")                                                   \
            for (int p = 0; p < 4; p++) {                                       \
                ldsm4(bhr[p], bB + OFF_BH + p * (16 * PITCH) + ks * 32);        \
                ldsm4(blr[p], bB + OFF_BL + p * (16 * PITCH) + ks * 32);        \
            }                                                                   \
            _Pragma("unroll")                                                   \
            for (int mt = 0; mt < 4; mt++)                                      \
                _Pragma("unroll")                                               \
                for (int nt = 0; nt < 8; nt++) {                                \
                    const uint32_t* bh2 = &bhr[nt >> 1][(nt & 1) * 2];          \
                    const uint32_t* bl2 = &blr[nt >> 1][(nt & 1) * 2];          \
                    mma_bf16(acc[mt][nt], ahr[mt], bh2);                        \
                    mma_bf16(acc[mt][nt], ahr[mt], bl2);                        \
                    mma_bf16(acc[mt][nt], alr[mt], bh2);                        \
                }                                                               \
        }                                                                       \
    }

__global__ __launch_bounds__(128, 2) void gemm_proj(
    const __nv_bfloat16* __restrict__ Ah, const __nv_bfloat16* __restrict__ Al,
    const __nv_bfloat16* __restrict__ Wh, const __nv_bfloat16* __restrict__ Wl,
    ProjOut po)
{
    extern __shared__ char sm[];
    const uint32_t sb = smem_u32(sm);
    const int tid = threadIdx.x, lane = tid & 31, wid = tid >> 5;
    const int wm = wid >> 1, wn = wid & 1;
    const int bm = blockIdx.y * 128, bn = blockIdx.x * 128;
    const int z = blockIdx.z;
    const __nv_bfloat16* Bh_ = Wh + (size_t)z * Dv * Dv;
    const __nv_bfloat16* Bl_ = Wl + (size_t)z * Dv * Dv;
    const float* bias = po.bias[z];
    __nv_bfloat16* Oh = po.oh[z];
    __nv_bfloat16* Ol = po.ol[z];
    const float oscale = (z == 0) ? 0.125f : 1.0f;

    GEMM_PROLOGUE_AND_LOOP(Ah, Al, Bh_, Bl_)

    const int g = lane >> 2, tg = lane & 3;
    #pragma unroll
    for (int nt = 0; nt < 8; nt++) {
        const int n0 = bn + wn * 64 + nt * 8 + tg * 2;
        const float b0 = __ldg(bias + n0), b1 = __ldg(bias + n0 + 1);
        const int h = n0 >> 6, d = n0 & 63;
        #pragma unroll
        for (int mt = 0; mt < 4; mt++) {
            const int mrow0 = bm + wm * 64 + mt * 16 + g;
            float v0 = fmaxf(acc[mt][nt][0] + b0, 0.f) * oscale;
            float v1 = fmaxf(acc[mt][nt][1] + b1, 0.f) * oscale;
            float v2 = fmaxf(acc[mt][nt][2] + b0, 0.f) * oscale;
            float v3 = fmaxf(acc[mt][nt][3] + b1, 0.f) * oscale;
            const size_t i0 = (((size_t)(mrow0 >> 11) * 16 + h) * 2048
                              + (mrow0 & 2047)) * 64 + d;
            const size_t i2 = i0 + 8 * 64;
            *(uint32_t*)(Oh + i0) = packf_hi(v0, v1);
            *(uint32_t*)(Ol + i0) = packf_lo(v0, v1);
            *(uint32_t*)(Oh + i2) = packf_hi(v2, v3);
            *(uint32_t*)(Ol + i2) = packf_lo(v2, v3);
        }
    }
}

__global__ __launch_bounds__(128, 2) void gemm_out(
    const __nv_bfloat16* __restrict__ Ah, const __nv_bfloat16* __restrict__ Al,
    const __nv_bfloat16* __restrict__ Bh_, const __nv_bfloat16* __restrict__ Bl_,
    const float* __restrict__ bias, float* __restrict__ C)
{
    extern __shared__ char sm[];
    const uint32_t sb = smem_u32(sm);
    const int tid = threadIdx.x, lane = tid & 31, wid = tid >> 5;
    const int wm = wid >> 1, wn = wid & 1;
    const int bm = blockIdx.y * 128, bn = blockIdx.x * 128;

    GEMM_PROLOGUE_AND_LOOP(Ah, Al, Bh_, Bl_)

    const int g = lane >> 2, tg = lane & 3;
    #pragma unroll
    for (int nt = 0; nt < 8; nt++) {
        const int n0 = bn + wn * 64 + nt * 8 + tg * 2;
        const float b0 = __ldg(bias + n0), b1 = __ldg(bias + n0 + 1);
        #pragma unroll
        for (int mt = 0; mt < 4; mt++) {
            const int mrow0 = bm + wm * 64 + mt * 16 + g;
            float2 o;
            o.x = fmaxf(acc[mt][nt][0] + b0, 0.f);
            o.y = fmaxf(acc[mt][nt][1] + b1, 0.f);
            *(float2*)(C + (size_t)mrow0 * Dv + n0) = o;
            o.x = fmaxf(acc[mt][nt][2] + b0, 0.f);
            o.y = fmaxf(acc[mt][nt][3] + b1, 0.f);
            *(float2*)(C + (size_t)(mrow0 + 8) * Dv + n0) = o;
        }
    }
}

// ================== tensor-core flash attention (R10 + 3-stage) =============
// 128 q rows/CTA, 2-term PV, exp-skip, single barrier per tile.
// 3-stage K/V ring with prefetch distance 2 (wait_group 1 keeps one group
// in flight) — each prefetch gets two tile-compute durations to land.
// 2 CTAs/SM: smem 108KB*2 = 216KB; launch_bounds pins regs<=128.
#define AP   144
#define AST  36864
#define A_KH 0
#define A_KL 9216
#define A_VH 18432
#define A_VL 27648
#define SMEM_A (3 * AST)          // 110592

__global__ __launch_bounds__(256, 2) void attn_mma(
    const __nv_bfloat16* __restrict__ Qh, const __nv_bfloat16* __restrict__ Ql,
    const __nv_bfloat16* __restrict__ Kh, const __nv_bfloat16* __restrict__ Kl,
    const __nv_bfloat16* __restrict__ Vh, const __nv_bfloat16* __restrict__ Vl,
    __nv_bfloat16* __restrict__ Chi, __nv_bfloat16* __restrict__ Clo)
{
    extern __shared__ char sm[];
    const uint32_t sb = smem_u32(sm);
    const int tid = threadIdx.x, lane = tid & 31, wid = tid >> 5;
    const int bx = blockIdx.x, bh = blockIdx.y;
    const size_t hbase = (size_t)bh * (Sv * HDv);
    const int g = lane >> 2, tg = lane & 3;

    // ---- stage Q into smem (stage0 area), then ldmatrix to regs ----
    #pragma unroll
    for (int c = tid; c < 1024; c += 256) {
        const int row = c >> 3, col = (c & 7) * 16;
        const size_t gsrc = hbase + (size_t)(bx * 128 + row) * 64 + (c & 7) * 8;
        cpa16(sb + row * AP + col, Qh + gsrc);
        cpa16(sb + 18432 + row * AP + col, Ql + gsrc);
    }
    CP_COMMIT(); CP_WAIT0();
    __syncthreads();

    uint32_t qh[4][4], ql[4][4];
    {
        const uint32_t aAddr = sb + (wid * 16 + (lane & 15)) * AP + (lane >> 4) * 16;
        #pragma unroll
        for (int kb = 0; kb < 4; kb++) {
            ldsm4(qh[kb], aAddr + kb * 32);
            ldsm4(ql[kb], aAddr + 18432 + kb * 32);
        }
    }
    __syncthreads();   // all warps consumed Q before tile-0 prefetch overwrites

    float m0 = -1e30f, m1 = -1e30f, l0 = 0.f, l1 = 0.f;
    float ctx[8][4];
    #pragma unroll
    for (int i = 0; i < 8; i++)
        #pragma unroll
        for (int j = 0; j < 4; j++) ctx[i][j] = 0.f;

    const int qg0 = bx * 128 + wid * 16 + g;
    const int qg8 = qg0 + 8;
    const int lastPV = 2 * bx + 1;

    // prologue: prefetch tiles 0 and 1 (both always causal-full: lastPV >= 1)
    #pragma unroll
    for (int ps = 0; ps < 2; ps++) {
        const uint32_t s = sb + ps * AST;
        const size_t rb = hbase + (size_t)ps * 64 * 64;
        #pragma unroll
        for (int c = tid; c < 512; c += 256) {
            const int row = c >> 3;
            const uint32_t col = (uint32_t)((c & 7) * 16);
            const size_t gs = rb + (size_t)row * 64 + (c & 7) * 8;
            cpa16(s + A_KH + row * AP + col, Kh + gs);
            cpa16(s + A_KL + row * AP + col, Kl + gs);
            cpa16(s + A_VH + row * AP + col, Vh + gs);
            cpa16(s + A_VL + row * AP + col, Vl + gs);
        }
        CP_COMMIT();
    }

    const uint32_t kPat = (uint32_t)(((lane >> 4) * 8 + (lane & 7)) * AP
                                     + ((lane >> 3) & 1) * 16);
    const uint32_t vPat = (uint32_t)(((lane & 7) + ((lane >> 3) & 1) * 8) * AP
                                     + (lane >> 4) * 16);

    int stage = 0, pstage = 2;
    #pragma unroll 1
    for (int kt = 0; kt < 32; kt++) {
        // tile kt's group is complete after wait1: the only group allowed to
        // remain in flight is the most recent one (tile kt+1's).
        if (kt < 31) { CP_WAIT1(); } else { CP_WAIT0(); }
        __syncthreads();   // orders compute(kt-1) before pstage overwrite below

        // prefetch tile kt+2 into the stage consumed at iter kt-1
        if (kt + 2 < 32) {
            const int nt_ = kt + 2;
            const uint32_t s = sb + pstage * AST;
            const size_t rb = hbase + (size_t)nt_ * 64 * 64;
            const bool full = (nt_ <= lastPV);
            #pragma unroll
            for (int c = tid; c < 512; c += 256) {
                const int row = c >> 3;
                const uint32_t col = (uint32_t)((c & 7) * 16);
                const size_t gs = rb + (size_t)row * 64 + (c & 7) * 8;
                cpa16(s + A_KH + row * AP + col, Kh + gs);
                if (full) {
                    cpa16(s + A_KL + row * AP + col, Kl + gs);
                    cpa16(s + A_VH + row * AP + col, Vh + gs);
                    cpa16(s + A_VL + row * AP + col, Vl + gs);
                }
            }
            CP_COMMIT();
        }

        const uint32_t base = sb + stage * AST;
        const bool fut = (kt > lastPV);

        float S[8][4];
        #pragma unroll
        for (int i = 0; i < 8; i++)
            #pragma unroll
            for (int j = 0; j < 4; j++) S[i][j] = 0.f;

        const uint32_t kAddr = base + kPat;
        #pragma unroll
        for (int nb = 0; nb < 4; nb++) {
            #pragma unroll
            for (int kb = 0; kb < 4; kb++) {
                uint32_t rh[4];
                ldsm4(rh, kAddr + A_KH + nb * (16 * AP) + kb * 32);
                mma_bf16(S[2 * nb], qh[kb], rh + 0);
                mma_bf16(S[2 * nb + 1], qh[kb], rh + 2);
                mma_bf16(S[2 * nb], ql[kb], rh + 0);
                mma_bf16(S[2 * nb + 1], ql[kb], rh + 2);
                if (!fut) {
                    uint32_t rl[4];
                    ldsm4(rl, kAddr + A_KL + nb * (16 * AP) + kb * 32);
                    mma_bf16(S[2 * nb], qh[kb], rl + 0);
                    mma_bf16(S[2 * nb + 1], qh[kb], rl + 2);
                }
            }
        }

        float rm0 = -1e30f, rm1 = -1e30f;
        #pragma unroll
        for (int i = 0; i < 8; i++) {
            rm0 = fmaxf(rm0, fmaxf(S[i][0], S[i][1]));
            rm1 = fmaxf(rm1, fmaxf(S[i][2], S[i][3]));
        }
        rm0 = fmaxf(rm0, __shfl_xor_sync(0xffffffffu, rm0, 1));
        rm0 = fmaxf(rm0, __shfl_xor_sync(0xffffffffu, rm0, 2));
        rm1 = fmaxf(rm1, __shfl_xor_sync(0xffffffffu, rm1, 1));
        rm1 = fmaxf(rm1, __shfl_xor_sync(0xffffffffu, rm1, 2));
        if (rm0 > m0 || rm1 > m1) {
            const float M0 = fmaxf(m0, rm0);
            const float M1 = fmaxf(m1, rm1);
            const float f0 = __expf(m0 - M0);
            const float f1 = __expf(m1 - M1);
            l0 *= f0; l1 *= f1;
            #pragma unroll
            for (int i = 0; i < 8; i++) {
                ctx[i][0] *= f0; ctx[i][1] *= f0;
                ctx[i][2] *= f1; ctx[i][3] *= f1;
            }
            m0 = M0; m1 = M1;
        }

        if (!fut) {
            uint32_t ph[8][2];
            const int jb = kt * 64 + 2 * tg;
            #pragma unroll
            for (int nt = 0; nt < 8; nt++) {
                const int j0 = jb + nt * 8;
                const float p0 = (j0 <= qg0) ? __expf(S[nt][0] - m0) : 0.f;
                const float p1 = (j0 + 1 <= qg0) ? __expf(S[nt][1] - m0) : 0.f;
                const float p2 = (j0 <= qg8) ? __expf(S[nt][2] - m1) : 0.f;
                const float p3 = (j0 + 1 <= qg8) ? __expf(S[nt][3] - m1) : 0.f;
                l0 += p0 + p1; l1 += p2 + p3;
                ph[nt][0] = packf_hi(p0, p1);
                ph[nt][1] = packf_hi(p2, p3);
            }
            const uint32_t vAddr = base + vPat;
            #pragma unroll
            for (int kk = 0; kk < 4; kk++) {
                uint32_t Ahh[4] = { ph[2 * kk][0], ph[2 * kk][1],
                                    ph[2 * kk + 1][0], ph[2 * kk + 1][1] };
                #pragma unroll
                for (int db = 0; db < 4; db++) {
                    uint32_t vh4[4], vl4[4];
                    const uint32_t va = vAddr + kk * (16 * AP) + db * 32;
                    ldsm4t(vh4, va + A_VH);
                    ldsm4t(vl4, va + A_VL);
                    mma_bf16(ctx[2 * db], Ahh, vh4 + 0);
                    mma_bf16(ctx[2 * db + 1], Ahh, vh4 + 2);
                    mma_bf16(ctx[2 * db], Ahh, vl4 + 0);
                    mma_bf16(ctx[2 * db + 1], Ahh, vl4 + 2);
                }
            }
        }
        stage = (stage + 1 == 3) ? 0 : stage + 1;
        pstage = (pstage + 1 == 3) ? 0 : pstage + 1;
    }

    l0 += __shfl_xor_sync(0xffffffffu, l0, 1);
    l0 += __shfl_xor_sync(0xffffffffu, l0, 2);
    l1 += __shfl_xor_sync(0xffffffffu, l1, 1);
    l1 += __shfl_xor_sync(0xffffffffu, l1, 2);
    const float inv0 = 1.0f / (l0 + EPSv);
    const float inv1 = 1.0f / (l1 + EPSv);

    const int b = bh >> 4, h = bh & 15;
    const size_t o0 = ((size_t)(b * Sv + qg0)) * Dv + h * 64;
    const size_t o8 = ((size_t)(b * Sv + qg8)) * Dv + h * 64;
    #pragma unroll
    for (int nt = 0; nt < 8; nt++) {
        const int d0 = nt * 8 + tg * 2;
        const float v0 = ctx[nt][0] * inv0, v1 = ctx[nt][1] * inv0;
        const float v2 = ctx[nt][2] * inv1, v3 = ctx[nt][3] * inv1;
        *(uint32_t*)(Chi + o0 + d0) = packf_hi(v0, v1);
        *(uint32_t*)(Clo + o0 + d0) = packf_lo(v0, v1);
        *(uint32_t*)(Chi + o8 + d0) = packf_hi(v2, v3);
        *(uint32_t*)(Clo + o8 + d0) = packf_lo(v2, v3);
    }
}

// ---------------- launch -----------------------------------------------------
extern "C" void kernel_launch(void* const* d_in, const int* in_sizes, int n_in,
                              void* d_out, int out_size)
{
    const float* x  = (const float*)d_in[0];
    const float* Wq = (const float*)d_in[1];
    const float* bq = (const float*)d_in[2];
    const float* Wk = (const float*)d_in[3];
    const float* bk = (const float*)d_in[4];
    const float* Wv = (const float*)d_in[5];
    const float* bv = (const float*)d_in[6];
    const float* Wo = (const float*)d_in[7];
    const float* bo = (const float*)d_in[8];
    float* out = (float*)d_out;

    __nv_bfloat16 *xhi, *xlo, *wh, *wl;
    __nv_bfloat16 *qhi, *qlo, *khi, *klo, *vhi, *vlo, *chi, *clo;
    cudaGetSymbolAddress((void**)&xhi, g_xhi);
    cudaGetSymbolAddress((void**)&xlo, g_xlo);
    cudaGetSymbolAddress((void**)&wh,  g_wh);
    cudaGetSymbolAddress((void**)&wl,  g_wl);
    cudaGetSymbolAddress((void**)&qhi, g_qhi);
    cudaGetSymbolAddress((void**)&qlo, g_qlo);
    cudaGetSymbolAddress((void**)&khi, g_khi);
    cudaGetSymbolAddress((void**)&klo, g_klo);
    cudaGetSymbolAddress((void**)&vhi, g_vhi);
    cudaGetSymbolAddress((void**)&vlo, g_vlo);
    cudaGetSymbolAddress((void**)&chi, g_chi);
    cudaGetSymbolAddress((void**)&clo, g_clo);

    cudaFuncSetAttribute(gemm_proj, cudaFuncAttributeMaxDynamicSharedMemorySize, SMEM_G);
    cudaFuncSetAttribute(gemm_out, cudaFuncAttributeMaxDynamicSharedMemorySize, SMEM_G);
    cudaFuncSetAttribute(attn_mma, cudaFuncAttributeMaxDynamicSharedMemorySize, SMEM_A);

    const int n4 = Mv * Dv / 4;
    split_rm<<<n4 / 256, 256>>>((const float4*)x, (__nv_bfloat162*)xhi,
                                (__nv_bfloat162*)xlo, n4);

    WSrc ws;
    ws.w[0] = Wq; ws.w[1] = Wk; ws.w[2] = Wv; ws.w[3] = Wo;
    dim3 tgrid(Dv / 32, Dv / 32, 4);
    tsplit4<<<tgrid, 256>>>(ws, wh, wl);

    ProjOut po;
    po.bias[0] = bq; po.bias[1] = bk; po.bias[2] = bv;
    po.oh[0] = qhi; po.oh[1] = khi; po.oh[2] = vhi;
    po.ol[0] = qlo; po.ol[1] = klo; po.ol[2] = vlo;

    dim3 pgrid(Dv / 128, Mv / 128, 3);   // fused Q/K/V
    gemm_proj<<<pgrid, 128, SMEM_G>>>(xhi, xlo, wh, wl, po);

    dim3 agrid(Sv / 128, Bv * Hv);       // (16, 64)
    attn_mma<<<agrid, 256, SMEM_A>>>(qhi, qlo, khi, klo, vhi, vlo, chi, clo);

    dim3 ggrid(Dv / 128, Mv / 128);
    gemm_out<<<ggrid, 128, SMEM_G>>>(chi, clo, wh + 3 * (size_t)Dv * Dv,
                                     wl + 3 * (size_t)Dv * Dv, bo, out);
}

// round 15
// speedup vs baseline: 1.5348x; 1.5348x over previous
#include <cuda_runtime.h>
#include <cuda_bf16.h>
#include <math.h>
#include <stdint.h>

#define Bv 4
#define Sv 2048
#define Dv 1024
#define Hv 16
#define HDv 64
#define Mv (Bv * Sv)          // 8192
#define EPSv 1e-7f

// ---------------- scratch (static device memory; no allocs) ----------------
__device__ __nv_bfloat16 g_xhi[Mv * Dv], g_xlo[Mv * Dv];
__device__ __nv_bfloat16 g_wh[4][Dv * Dv], g_wl[4][Dv * Dv];  // transposed [N][K]
__device__ __nv_bfloat16 g_qhi[Mv * Dv], g_qlo[Mv * Dv];
__device__ __nv_bfloat16 g_khi[Mv * Dv], g_klo[Mv * Dv];
__device__ __nv_bfloat16 g_vhi[Mv * Dv], g_vlo[Mv * Dv];
__device__ __nv_bfloat16 g_chi[Mv * Dv], g_clo[Mv * Dv];

struct ProjOut {
    const float* bias[3];
    __nv_bfloat16* oh[3];
    __nv_bfloat16* ol[3];
};
struct WSrc { const float* w[4]; };

// ======================= helpers ===========================================
__device__ __forceinline__ uint32_t smem_u32(const void* p) {
    uint32_t a;
    asm("{ .reg .u64 t; cvta.to.shared.u64 t, %1; cvt.u32.u64 %0, t; }"
        : "=r"(a) : "l"(p));
    return a;
}

__device__ __forceinline__ void cpa16(uint32_t d, const void* g) {
    asm volatile("cp.async.cg.shared.global [%0], [%1], 16;" :: "r"(d), "l"(g));
}
#define CP_COMMIT() asm volatile("cp.async.commit_group;" ::: "memory")
#define CP_WAIT0()  asm volatile("cp.async.wait_group 0;" ::: "memory")
#define CP_WAIT1()  asm volatile("cp.async.wait_group 1;" ::: "memory")

__device__ __forceinline__ void ldsm4(uint32_t* r, uint32_t a) {
    asm volatile("ldmatrix.sync.aligned.m8n8.x4.shared.b16 {%0,%1,%2,%3}, [%4];"
        : "=r"(r[0]), "=r"(r[1]), "=r"(r[2]), "=r"(r[3]) : "r"(a));
}
__device__ __forceinline__ void ldsm4t(uint32_t* r, uint32_t a) {
    asm volatile("ldmatrix.sync.aligned.m8n8.x4.trans.shared.b16 {%0,%1,%2,%3}, [%4];"
        : "=r"(r[0]), "=r"(r[1]), "=r"(r[2]), "=r"(r[3]) : "r"(a));
}

__device__ __forceinline__ void mma_bf16(float* d, const uint32_t* a, const uint32_t* b) {
    asm volatile(
        "mma.sync.aligned.m16n8k16.row.col.f32.bf16.bf16.f32 "
        "{%0,%1,%2,%3}, {%4,%5,%6,%7}, {%8,%9}, {%0,%1,%2,%3};"
        : "+f"(d[0]), "+f"(d[1]), "+f"(d[2]), "+f"(d[3])
        : "r"(a[0]), "r"(a[1]), "r"(a[2]), "r"(a[3]), "r"(b[0]), "r"(b[1]));
}

__device__ __forceinline__ uint32_t packf_hi(float a, float b) {
    __nv_bfloat162 t;
    t.x = __float2bfloat16(a); t.y = __float2bfloat16(b);
    return *reinterpret_cast<uint32_t*>(&t);
}
__device__ __forceinline__ uint32_t packf_lo(float a, float b) {
    __nv_bfloat162 t;
    t.x = __float2bfloat16(a - __bfloat162float(__float2bfloat16(a)));
    t.y = __float2bfloat16(b - __bfloat162float(__float2bfloat16(b)));
    return *reinterpret_cast<uint32_t*>(&t);
}

// ---------------- convert kernels ------------------------------------------
__global__ __launch_bounds__(256) void split_rm(
    const float4* __restrict__ src, __nv_bfloat162* __restrict__ hi,
    __nv_bfloat162* __restrict__ lo, int n4)
{
    int i = blockIdx.x * 256 + threadIdx.x;
    if (i >= n4) return;
    float4 v = src[i];
    __nv_bfloat16 h0 = __float2bfloat16(v.x), h1 = __float2bfloat16(v.y);
    __nv_bfloat16 h2 = __float2bfloat16(v.z), h3 = __float2bfloat16(v.w);
    __nv_bfloat162 a; a.x = h0; a.y = h1;
    __nv_bfloat162 b; b.x = h2; b.y = h3;
    hi[2 * i] = a; hi[2 * i + 1] = b;
    a.x = __float2bfloat16(v.x - __bfloat162float(h0));
    a.y = __float2bfloat16(v.y - __bfloat162float(h1));
    b.x = __float2bfloat16(v.z - __bfloat162float(h2));
    b.y = __float2bfloat16(v.w - __bfloat162float(h3));
    lo[2 * i] = a; lo[2 * i + 1] = b;
}

// all 4 weights: [K][N] row-major -> transposed bf16 hi/lo [N][K], grid.z picks W
__global__ __launch_bounds__(256) void tsplit4(
    WSrc ws, __nv_bfloat16* __restrict__ th4, __nv_bfloat16* __restrict__ tl4)
{
    __shared__ float t[32][33];
    const float* W = ws.w[blockIdx.z];
    __nv_bfloat16* th = th4 + (size_t)blockIdx.z * Dv * Dv;
    __nv_bfloat16* tl = tl4 + (size_t)blockIdx.z * Dv * Dv;
    const int n0 = blockIdx.x * 32, k0 = blockIdx.y * 32;
    const int tx = threadIdx.x & 31, ty = threadIdx.x >> 5;
    #pragma unroll
    for (int r = ty; r < 32; r += 8)
        t[r][tx] = W[(size_t)(k0 + r) * Dv + n0 + tx];
    __syncthreads();
    #pragma unroll
    for (int r = ty; r < 32; r += 8) {
        float v = t[tx][r];
        __nv_bfloat16 h = __float2bfloat16(v);
        th[(size_t)(n0 + r) * Dv + k0 + tx] = h;
        tl[(size_t)(n0 + r) * Dv + k0 + tx] = __float2bfloat16(v - __bfloat162float(h));
    }
}

// ================== mma.sync split-bf16 GEMM (R10, unchanged) ===============
#define NIT   32
#define PITCH 80
#define OFF_AH 0
#define OFF_AL 10240
#define OFF_BH 20480
#define OFF_BL 30720
#define STG    40960
#define SMEM_G (2 * STG)

#define GEMM_PROLOGUE_AND_LOOP(Ah_, Al_, Bh_, Bl_)                              \
    float acc[4][8][4];                                                         \
    _Pragma("unroll")                                                           \
    for (int i = 0; i < 4; i++)                                                 \
        _Pragma("unroll")                                                       \
        for (int j = 0; j < 8; j++) {                                           \
            acc[i][j][0] = 0.f; acc[i][j][1] = 0.f;                             \
            acc[i][j][2] = 0.f; acc[i][j][3] = 0.f;                             \
        }                                                                       \
    const int crow[4] = { tid >> 2, (tid + 128) >> 2, (tid + 256) >> 2,         \
                          (tid + 384) >> 2 };                                   \
    const int kc = tid & 3;                                                     \
    uint32_t soX[4]; size_t gaX[4], gbX[4];                                     \
    _Pragma("unroll")                                                           \
    for (int t = 0; t < 4; t++) {                                               \
        soX[t] = (uint32_t)(crow[t] * PITCH + kc * 16);                         \
        gaX[t] = (size_t)(bm + crow[t]) * Dv + kc * 8;                          \
        gbX[t] = (size_t)(bn + crow[t]) * Dv + kc * 8;                          \
    }                                                                           \
    const uint32_t aByte = (uint32_t)((wm * 64 + (lane & 15)) * PITCH           \
                                      + (lane >> 4) * 16);                      \
    const uint32_t bByte = (uint32_t)((wn * 64 + (lane >> 4) * 8 + (lane & 7))  \
                                      * PITCH + ((lane >> 3) & 1) * 16);        \
    {   /* prologue: stage 0 */                                                 \
        const uint32_t s = sb;                                                  \
        _Pragma("unroll")                                                       \
        for (int t = 0; t < 4; t++) {                                           \
            cpa16(s + OFF_AH + soX[t], Ah_ + gaX[t]);                           \
            cpa16(s + OFF_AL + soX[t], Al_ + gaX[t]);                           \
            cpa16(s + OFF_BH + soX[t], Bh_ + gbX[t]);                           \
            cpa16(s + OFF_BL + soX[t], Bl_ + gbX[t]);                           \
        }                                                                       \
        CP_COMMIT();                                                            \
    }                                                                           \
    _Pragma("unroll 1")                                                         \
    for (int it = 0; it < NIT; it++) {                                          \
        CP_WAIT0();                                                             \
        __syncthreads();                                                        \
        if (it + 1 < NIT) {                                                     \
            const int k0 = (it + 1) * 32;                                       \
            const uint32_t s = sb + ((it + 1) & 1) * STG;                       \
            _Pragma("unroll")                                                   \
            for (int t = 0; t < 4; t++) {                                       \
                cpa16(s + OFF_AH + soX[t], Ah_ + gaX[t] + k0);                  \
                cpa16(s + OFF_AL + soX[t], Al_ + gaX[t] + k0);                  \
                cpa16(s + OFF_BH + soX[t], Bh_ + gbX[t] + k0);                  \
                cpa16(s + OFF_BL + soX[t], Bl_ + gbX[t] + k0);                  \
            }                                                                   \
            CP_COMMIT();                                                        \
        }                                                                       \
        const uint32_t aB = sb + (it & 1) * STG + aByte;                        \
        const uint32_t bB = sb + (it & 1) * STG + bByte;                        \
        _Pragma("unroll")                                                       \
        for (int ks = 0; ks < 2; ks++) {                                        \
            uint32_t ahr[4][4], alr[4][4], bhr[4][4], blr[4][4];                \
            _Pragma("unroll")                                                   \
            for (int mt = 0; mt < 4; mt++) {                                    \
                ldsm4(ahr[mt], aB + OFF_AH + mt * (16 * PITCH) + ks * 32);      \
                ldsm4(alr[mt], aB + OFF_AL + mt * (16 * PITCH) + ks * 32);      \
            }                                                                   \
            _Pragma("unroll")                                                   \
            for (int p = 0; p < 4; p++) {                                       \
                ldsm4(bhr[p], bB + OFF_BH + p * (16 * PITCH) + ks * 32);        \
                ldsm4(blr[p], bB + OFF_BL + p * (16 * PITCH) + ks * 32);        \
            }                                                                   \
            _Pragma("unroll")                                                   \
            for (int mt = 0; mt < 4; mt++)                                      \
                _Pragma("unroll")                                               \
                for (int nt = 0; nt < 8; nt++) {                                \
                    const uint32_t* bh2 = &bhr[nt >> 1][(nt & 1) * 2];          \
                    const uint32_t* bl2 = &blr[nt >> 1][(nt & 1) * 2];          \
                    mma_bf16(acc[mt][nt], ahr[mt], bh2);                        \
                    mma_bf16(acc[mt][nt], ahr[mt], bl2);                        \
                    mma_bf16(acc[mt][nt], alr[mt], bh2);                        \
                }                                                               \
        }                                                                       \
    }

__global__ __launch_bounds__(128, 2) void gemm_proj(
    const __nv_bfloat16* __restrict__ Ah, const __nv_bfloat16* __restrict__ Al,
    const __nv_bfloat16* __restrict__ Wh, const __nv_bfloat16* __restrict__ Wl,
    ProjOut po)
{
    extern __shared__ char sm[];
    const uint32_t sb = smem_u32(sm);
    const int tid = threadIdx.x, lane = tid & 31, wid = tid >> 5;
    const int wm = wid >> 1, wn = wid & 1;
    const int bm = blockIdx.y * 128, bn = blockIdx.x * 128;
    const int z = blockIdx.z;
    const __nv_bfloat16* Bh_ = Wh + (size_t)z * Dv * Dv;
    const __nv_bfloat16* Bl_ = Wl + (size_t)z * Dv * Dv;
    const float* bias = po.bias[z];
    __nv_bfloat16* Oh = po.oh[z];
    __nv_bfloat16* Ol = po.ol[z];
    const float oscale = (z == 0) ? 0.125f : 1.0f;

    GEMM_PROLOGUE_AND_LOOP(Ah, Al, Bh_, Bl_)

    const int g = lane >> 2, tg = lane & 3;
    #pragma unroll
    for (int nt = 0; nt < 8; nt++) {
        const int n0 = bn + wn * 64 + nt * 8 + tg * 2;
        const float b0 = __ldg(bias + n0), b1 = __ldg(bias + n0 + 1);
        const int h = n0 >> 6, d = n0 & 63;
        #pragma unroll
        for (int mt = 0; mt < 4; mt++) {
            const int mrow0 = bm + wm * 64 + mt * 16 + g;
            float v0 = fmaxf(acc[mt][nt][0] + b0, 0.f) * oscale;
            float v1 = fmaxf(acc[mt][nt][1] + b1, 0.f) * oscale;
            float v2 = fmaxf(acc[mt][nt][2] + b0, 0.f) * oscale;
            float v3 = fmaxf(acc[mt][nt][3] + b1, 0.f) * oscale;
            const size_t i0 = (((size_t)(mrow0 >> 11) * 16 + h) * 2048
                              + (mrow0 & 2047)) * 64 + d;
            const size_t i2 = i0 + 8 * 64;
            *(uint32_t*)(Oh + i0) = packf_hi(v0, v1);
            *(uint32_t*)(Ol + i0) = packf_lo(v0, v1);
            *(uint32_t*)(Oh + i2) = packf_hi(v2, v3);
            *(uint32_t*)(Ol + i2) = packf_lo(v2, v3);
        }
    }
}

__global__ __launch_bounds__(128, 2) void gemm_out(
    const __nv_bfloat16* __restrict__ Ah, const __nv_bfloat16* __restrict__ Al,
    const __nv_bfloat16* __restrict__ Bh_, const __nv_bfloat16* __restrict__ Bl_,
    const float* __restrict__ bias, float* __restrict__ C)
{
    extern __shared__ char sm[];
    const uint32_t sb = smem_u32(sm);
    const int tid = threadIdx.x, lane = tid & 31, wid = tid >> 5;
    const int wm = wid >> 1, wn = wid & 1;
    const int bm = blockIdx.y * 128, bn = blockIdx.x * 128;

    GEMM_PROLOGUE_AND_LOOP(Ah, Al, Bh_, Bl_)

    const int g = lane >> 2, tg = lane & 3;
    #pragma unroll
    for (int nt = 0; nt < 8; nt++) {
        const int n0 = bn + wn * 64 + nt * 8 + tg * 2;
        const float b0 = __ldg(bias + n0), b1 = __ldg(bias + n0 + 1);
        #pragma unroll
        for (int mt = 0; mt < 4; mt++) {
            const int mrow0 = bm + wm * 64 + mt * 16 + g;
            float2 o;
            o.x = fmaxf(acc[mt][nt][0] + b0, 0.f);
            o.y = fmaxf(acc[mt][nt][1] + b1, 0.f);
            *(float2*)(C + (size_t)mrow0 * Dv + n0) = o;
            o.x = fmaxf(acc[mt][nt][2] + b0, 0.f);
            o.y = fmaxf(acc[mt][nt][3] + b1, 0.f);
            *(float2*)(C + (size_t)(mrow0 + 8) * Dv + n0) = o;
        }
    }
}

// ================== tensor-core flash attention (R13, re-bench) =============
// 128 q rows/CTA, 2-term PV, exp-skip, single barrier per tile.
// 3-stage K/V ring with prefetch distance 2.
#define AP   144
#define AST  36864
#define A_KH 0
#define A_KL 9216
#define A_VH 18432
#define A_VL 27648
#define SMEM_A (3 * AST)          // 110592

__global__ __launch_bounds__(256, 2) void attn_mma(
    const __nv_bfloat16* __restrict__ Qh, const __nv_bfloat16* __restrict__ Ql,
    const __nv_bfloat16* __restrict__ Kh, const __nv_bfloat16* __restrict__ Kl,
    const __nv_bfloat16* __restrict__ Vh, const __nv_bfloat16* __restrict__ Vl,
    __nv_bfloat16* __restrict__ Chi, __nv_bfloat16* __restrict__ Clo)
{
    extern __shared__ char sm[];
    const uint32_t sb = smem_u32(sm);
    const int tid = threadIdx.x, lane = tid & 31, wid = tid >> 5;
    const int bx = blockIdx.x, bh = blockIdx.y;
    const size_t hbase = (size_t)bh * (Sv * HDv);
    const int g = lane >> 2, tg = lane & 3;

    // ---- stage Q into smem (stage0 area), then ldmatrix to regs ----
    #pragma unroll
    for (int c = tid; c < 1024; c += 256) {
        const int row = c >> 3, col = (c & 7) * 16;
        const size_t gsrc = hbase + (size_t)(bx * 128 + row) * 64 + (c & 7) * 8;
        cpa16(sb + row * AP + col, Qh + gsrc);
        cpa16(sb + 18432 + row * AP + col, Ql + gsrc);
    }
    CP_COMMIT(); CP_WAIT0();
    __syncthreads();

    uint32_t qh[4][4], ql[4][4];
    {
        const uint32_t aAddr = sb + (wid * 16 + (lane & 15)) * AP + (lane >> 4) * 16;
        #pragma unroll
        for (int kb = 0; kb < 4; kb++) {
            ldsm4(qh[kb], aAddr + kb * 32);
            ldsm4(ql[kb], aAddr + 18432 + kb * 32);
        }
    }
    __syncthreads();   // all warps consumed Q before tile-0 prefetch overwrites

    float m0 = -1e30f, m1 = -1e30f, l0 = 0.f, l1 = 0.f;
    float ctx[8][4];
    #pragma unroll
    for (int i = 0; i < 8; i++)
        #pragma unroll
        for (int j = 0; j < 4; j++) ctx[i][j] = 0.f;

    const int qg0 = bx * 128 + wid * 16 + g;
    const int qg8 = qg0 + 8;
    const int lastPV = 2 * bx + 1;

    // prologue: prefetch tiles 0 and 1 (both always causal-full: lastPV >= 1)
    #pragma unroll
    for (int ps = 0; ps < 2; ps++) {
        const uint32_t s = sb + ps * AST;
        const size_t rb = hbase + (size_t)ps * 64 * 64;
        #pragma unroll
        for (int c = tid; c < 512; c += 256) {
            const int row = c >> 3;
            const uint32_t col = (uint32_t)((c & 7) * 16);
            const size_t gs = rb + (size_t)row * 64 + (c & 7) * 8;
            cpa16(s + A_KH + row * AP + col, Kh + gs);
            cpa16(s + A_KL + row * AP + col, Kl + gs);
            cpa16(s + A_VH + row * AP + col, Vh + gs);
            cpa16(s + A_VL + row * AP + col, Vl + gs);
        }
        CP_COMMIT();
    }

    const uint32_t kPat = (uint32_t)(((lane >> 4) * 8 + (lane & 7)) * AP
                                     + ((lane >> 3) & 1) * 16);
    const uint32_t vPat = (uint32_t)(((lane & 7) + ((lane >> 3) & 1) * 8) * AP
                                     + (lane >> 4) * 16);

    int stage = 0, pstage = 2;
    #pragma unroll 1
    for (int kt = 0; kt < 32; kt++) {
        if (kt < 31) { CP_WAIT1(); } else { CP_WAIT0(); }
        __syncthreads();   // orders compute(kt-1) before pstage overwrite below

        // prefetch tile kt+2 into the stage consumed at iter kt-1
        if (kt + 2 < 32) {
            const int nt_ = kt + 2;
            const uint32_t s = sb + pstage * AST;
            const size_t rb = hbase + (size_t)nt_ * 64 * 64;
            const bool full = (nt_ <= lastPV);
            #pragma unroll
            for (int c = tid; c < 512; c += 256) {
                const int row = c >> 3;
                const uint32_t col = (uint32_t)((c & 7) * 16);
                const size_t gs = rb + (size_t)row * 64 + (c & 7) * 8;
                cpa16(s + A_KH + row * AP + col, Kh + gs);
                if (full) {
                    cpa16(s + A_KL + row * AP + col, Kl + gs);
                    cpa16(s + A_VH + row * AP + col, Vh + gs);
                    cpa16(s + A_VL + row * AP + col, Vl + gs);
                }
            }
            CP_COMMIT();
        }

        const uint32_t base = sb + stage * AST;
        const bool fut = (kt > lastPV);

        float S[8][4];
        #pragma unroll
        for (int i = 0; i < 8; i++)
            #pragma unroll
            for (int j = 0; j < 4; j++) S[i][j] = 0.f;

        const uint32_t kAddr = base + kPat;
        #pragma unroll
        for (int nb = 0; nb < 4; nb++) {
            #pragma unroll
            for (int kb = 0; kb < 4; kb++) {
                uint32_t rh[4];
                ldsm4(rh, kAddr + A_KH + nb * (16 * AP) + kb * 32);
                mma_bf16(S[2 * nb], qh[kb], rh + 0);
                mma_bf16(S[2 * nb + 1], qh[kb], rh + 2);
                mma_bf16(S[2 * nb], ql[kb], rh + 0);
                mma_bf16(S[2 * nb + 1], ql[kb], rh + 2);
                if (!fut) {
                    uint32_t rl[4];
                    ldsm4(rl, kAddr + A_KL + nb * (16 * AP) + kb * 32);
                    mma_bf16(S[2 * nb], qh[kb], rl + 0);
                    mma_bf16(S[2 * nb + 1], qh[kb], rl + 2);
                }
            }
        }

        float rm0 = -1e30f, rm1 = -1e30f;
        #pragma unroll
        for (int i = 0; i < 8; i++) {
            rm0 = fmaxf(rm0, fmaxf(S[i][0], S[i][1]));
            rm1 = fmaxf(rm1, fmaxf(S[i][2], S[i][3]));
        }
        rm0 = fmaxf(rm0, __shfl_xor_sync(0xffffffffu, rm0, 1));
        rm0 = fmaxf(rm0, __shfl_xor_sync(0xffffffffu, rm0, 2));
        rm1 = fmaxf(rm1, __shfl_xor_sync(0xffffffffu, rm1, 1));
        rm1 = fmaxf(rm1, __shfl_xor_sync(0xffffffffu, rm1, 2));
        if (rm0 > m0 || rm1 > m1) {
            const float M0 = fmaxf(m0, rm0);
            const float M1 = fmaxf(m1, rm1);
            const float f0 = __expf(m0 - M0);
            const float f1 = __expf(m1 - M1);
            l0 *= f0; l1 *= f1;
            #pragma unroll
            for (int i = 0; i < 8; i++) {
                ctx[i][0] *= f0; ctx[i][1] *= f0;
                ctx[i][2] *= f1; ctx[i][3] *= f1;
            }
            m0 = M0; m1 = M1;
        }

        if (!fut) {
            uint32_t ph[8][2];
            const int jb = kt * 64 + 2 * tg;
            #pragma unroll
            for (int nt = 0; nt < 8; nt++) {
                const int j0 = jb + nt * 8;
                const float p0 = (j0 <= qg0) ? __expf(S[nt][0] - m0) : 0.f;
                const float p1 = (j0 + 1 <= qg0) ? __expf(S[nt][1] - m0) : 0.f;
                const float p2 = (j0 <= qg8) ? __expf(S[nt][2] - m1) : 0.f;
                const float p3 = (j0 + 1 <= qg8) ? __expf(S[nt][3] - m1) : 0.f;
                l0 += p0 + p1; l1 += p2 + p3;
                ph[nt][0] = packf_hi(p0, p1);
                ph[nt][1] = packf_hi(p2, p3);
            }
            const uint32_t vAddr = base + vPat;
            #pragma unroll
            for (int kk = 0; kk < 4; kk++) {
                uint32_t Ahh[4] = { ph[2 * kk][0], ph[2 * kk][1],
                                    ph[2 * kk + 1][0], ph[2 * kk + 1][1] };
                #pragma unroll
                for (int db = 0; db < 4; db++) {
                    uint32_t vh4[4], vl4[4];
                    const uint32_t va = vAddr + kk * (16 * AP) + db * 32;
                    ldsm4t(vh4, va + A_VH);
                    ldsm4t(vl4, va + A_VL);
                    mma_bf16(ctx[2 * db], Ahh, vh4 + 0);
                    mma_bf16(ctx[2 * db + 1], Ahh, vh4 + 2);
                    mma_bf16(ctx[2 * db], Ahh, vl4 + 0);
                    mma_bf16(ctx[2 * db + 1], Ahh, vl4 + 2);
                }
            }
        }
        stage = (stage + 1 == 3) ? 0 : stage + 1;
        pstage = (pstage + 1 == 3) ? 0 : pstage + 1;
    }

    l0 += __shfl_xor_sync(0xffffffffu, l0, 1);
    l0 += __shfl_xor_sync(0xffffffffu, l0, 2);
    l1 += __shfl_xor_sync(0xffffffffu, l1, 1);
    l1 += __shfl_xor_sync(0xffffffffu, l1, 2);
    const float inv0 = 1.0f / (l0 + EPSv);
    const float inv1 = 1.0f / (l1 + EPSv);

    const int b = bh >> 4, h = bh & 15;
    const size_t o0 = ((size_t)(b * Sv + qg0)) * Dv + h * 64;
    const size_t o8 = ((size_t)(b * Sv + qg8)) * Dv + h * 64;
    #pragma unroll
    for (int nt = 0; nt < 8; nt++) {
        const int d0 = nt * 8 + tg * 2;
        const float v0 = ctx[nt][0] * inv0, v1 = ctx[nt][1] * inv0;
        const float v2 = ctx[nt][2] * inv1, v3 = ctx[nt][3] * inv1;
        *(uint32_t*)(Chi + o0 + d0) = packf_hi(v0, v1);
        *(uint32_t*)(Clo + o0 + d0) = packf_lo(v0, v1);
        *(uint32_t*)(Chi + o8 + d0) = packf_hi(v2, v3);
        *(uint32_t*)(Clo + o8 + d0) = packf_lo(v2, v3);
    }
}

// ---------------- launch -----------------------------------------------------
extern "C" void kernel_launch(void* const* d_in, const int* in_sizes, int n_in,
                              void* d_out, int out_size)
{
    const float* x  = (const float*)d_in[0];
    const float* Wq = (const float*)d_in[1];
    const float* bq = (const float*)d_in[2];
    const float* Wk = (const float*)d_in[3];
    const float* bk = (const float*)d_in[4];
    const float* Wv = (const float*)d_in[5];
    const float* bv = (const float*)d_in[6];
    const float* Wo = (const float*)d_in[7];
    const float* bo = (const float*)d_in[8];
    float* out = (float*)d_out;

    __nv_bfloat16 *xhi, *xlo, *wh, *wl;
    __nv_bfloat16 *qhi, *qlo, *khi, *klo, *vhi, *vlo, *chi, *clo;
    cudaGetSymbolAddress((void**)&xhi, g_xhi);
    cudaGetSymbolAddress((void**)&xlo, g_xlo);
    cudaGetSymbolAddress((void**)&wh,  g_wh);
    cudaGetSymbolAddress((void**)&wl,  g_wl);
    cudaGetSymbolAddress((void**)&qhi, g_qhi);
    cudaGetSymbolAddress((void**)&qlo, g_qlo);
    cudaGetSymbolAddress((void**)&khi, g_khi);
    cudaGetSymbolAddress((void**)&klo, g_klo);
    cudaGetSymbolAddress((void**)&vhi, g_vhi);
    cudaGetSymbolAddress((void**)&vlo, g_vlo);
    cudaGetSymbolAddress((void**)&chi, g_chi);
    cudaGetSymbolAddress((void**)&clo, g_clo);

    cudaFuncSetAttribute(gemm_proj, cudaFuncAttributeMaxDynamicSharedMemorySize, SMEM_G);
    cudaFuncSetAttribute(gemm_out, cudaFuncAttributeMaxDynamicSharedMemorySize, SMEM_G);
    cudaFuncSetAttribute(attn_mma, cudaFuncAttributeMaxDynamicSharedMemorySize, SMEM_A);

    const int n4 = Mv * Dv / 4;
    split_rm<<<n4 / 256, 256>>>((const float4*)x, (__nv_bfloat162*)xhi,
                                (__nv_bfloat162*)xlo, n4);

    WSrc ws;
    ws.w[0] = Wq; ws.w[1] = Wk; ws.w[2] = Wv; ws.w[3] = Wo;
    dim3 tgrid(Dv / 32, Dv / 32, 4);
    tsplit4<<<tgrid, 256>>>(ws, wh, wl);

    ProjOut po;
    po.bias[0] = bq; po.bias[1] = bk; po.bias[2] = bv;
    po.oh[0] = qhi; po.oh[1] = khi; po.oh[2] = vhi;
    po.ol[0] = qlo; po.ol[1] = klo; po.ol[2] = vlo;

    dim3 pgrid(Dv / 128, Mv / 128, 3);   // fused Q/K/V
    gemm_proj<<<pgrid, 128, SMEM_G>>>(xhi, xlo, wh, wl, po);

    dim3 agrid(Sv / 128, Bv * Hv);       // (16, 64)
    attn_mma<<<agrid, 256, SMEM_A>>>(qhi, qlo, khi, klo, vhi, vlo, chi, clo);

    dim3 ggrid(Dv / 128, Mv / 128);
    gemm_out<<<ggrid, 128, SMEM_G>>>(chi, clo, wh + 3 * (size_t)Dv * Dv,
                                     wl + 3 * (size_t)Dv * Dv, bo, out);
}

// round 16
// speedup vs baseline: 1.5557x; 1.0136x over previous
#include <cuda_runtime.h>
#include <cuda_bf16.h>
#include <math.h>
#include <stdint.h>

#define Bv 4
#define Sv 2048
#define Dv 1024
#define Hv 16
#define HDv 64
#define Mv (Bv * Sv)          // 8192
#define EPSv 1e-7f

// ---------------- scratch (static device memory; no allocs) ----------------
__device__ __nv_bfloat16 g_xhi[Mv * Dv], g_xlo[Mv * Dv];
__device__ __nv_bfloat16 g_wh[4][Dv * Dv], g_wl[4][Dv * Dv];  // transposed [N][K]
__device__ __nv_bfloat16 g_qhi[Mv * Dv], g_qlo[Mv * Dv];
__device__ __nv_bfloat16 g_khi[Mv * Dv], g_klo[Mv * Dv];
__device__ __nv_bfloat16 g_vhi[Mv * Dv], g_vlo[Mv * Dv];
__device__ __nv_bfloat16 g_chi[Mv * Dv], g_clo[Mv * Dv];

struct ProjOut {
    const float* bias[3];
    __nv_bfloat16* oh[3];
    __nv_bfloat16* ol[3];
};
struct WSrc { const float* w[4]; };

// ======================= helpers ===========================================
__device__ __forceinline__ uint32_t smem_u32(const void* p) {
    uint32_t a;
    asm("{ .reg .u64 t; cvta.to.shared.u64 t, %1; cvt.u32.u64 %0, t; }"
        : "=r"(a) : "l"(p));
    return a;
}

__device__ __forceinline__ void cpa16(uint32_t d, const void* g) {
    asm volatile("cp.async.cg.shared.global [%0], [%1], 16;" :: "r"(d), "l"(g));
}
#define CP_COMMIT() asm volatile("cp.async.commit_group;" ::: "memory")
#define CP_WAIT0()  asm volatile("cp.async.wait_group 0;" ::: "memory")
#define CP_WAIT1()  asm volatile("cp.async.wait_group 1;" ::: "memory")

__device__ __forceinline__ void ldsm4(uint32_t* r, uint32_t a) {
    asm volatile("ldmatrix.sync.aligned.m8n8.x4.shared.b16 {%0,%1,%2,%3}, [%4];"
        : "=r"(r[0]), "=r"(r[1]), "=r"(r[2]), "=r"(r[3]) : "r"(a));
}
__device__ __forceinline__ void ldsm4t(uint32_t* r, uint32_t a) {
    asm volatile("ldmatrix.sync.aligned.m8n8.x4.trans.shared.b16 {%0,%1,%2,%3}, [%4];"
        : "=r"(r[0]), "=r"(r[1]), "=r"(r[2]), "=r"(r[3]) : "r"(a));
}

__device__ __forceinline__ void mma_bf16(float* d, const uint32_t* a, const uint32_t* b) {
    asm volatile(
        "mma.sync.aligned.m16n8k16.row.col.f32.bf16.bf16.f32 "
        "{%0,%1,%2,%3}, {%4,%5,%6,%7}, {%8,%9}, {%0,%1,%2,%3};"
        : "+f"(d[0]), "+f"(d[1]), "+f"(d[2]), "+f"(d[3])
        : "r"(a[0]), "r"(a[1]), "r"(a[2]), "r"(a[3]), "r"(b[0]), "r"(b[1]));
}

// packed bf16x2 convert: d = {lo=cvt(a), hi=cvt(b)} — same rn rounding as
// __float2bfloat16, one instruction.
__device__ __forceinline__ uint32_t packf_hi(float a, float b) {
    uint32_t r;
    asm("cvt.rn.bf16x2.f32 %0, %2, %1;" : "=r"(r) : "f"(a), "f"(b));
    return r;
}
__device__ __forceinline__ uint32_t packf_lo(float a, float b) {
    const float ra = a - __bfloat162float(__float2bfloat16(a));
    const float rb = b - __bfloat162float(__float2bfloat16(b));
    uint32_t r;
    asm("cvt.rn.bf16x2.f32 %0, %2, %1;" : "=r"(r) : "f"(ra), "f"(rb));
    return r;
}

// ---------------- convert kernels ------------------------------------------
__global__ __launch_bounds__(256) void split_rm(
    const float4* __restrict__ src, __nv_bfloat162* __restrict__ hi,
    __nv_bfloat162* __restrict__ lo, int n4)
{
    int i = blockIdx.x * 256 + threadIdx.x;
    if (i >= n4) return;
    float4 v = src[i];
    uint32_t h01 = packf_hi(v.x, v.y), h23 = packf_hi(v.z, v.w);
    uint32_t l01 = packf_lo(v.x, v.y), l23 = packf_lo(v.z, v.w);
    ((uint32_t*)hi)[2 * i] = h01; ((uint32_t*)hi)[2 * i + 1] = h23;
    ((uint32_t*)lo)[2 * i] = l01; ((uint32_t*)lo)[2 * i + 1] = l23;
}

// all 4 weights: [K][N] row-major -> transposed bf16 hi/lo [N][K], grid.z picks W
__global__ __launch_bounds__(256) void tsplit4(
    WSrc ws, __nv_bfloat16* __restrict__ th4, __nv_bfloat16* __restrict__ tl4)
{
    __shared__ float t[32][33];
    const float* W = ws.w[blockIdx.z];
    __nv_bfloat16* th = th4 + (size_t)blockIdx.z * Dv * Dv;
    __nv_bfloat16* tl = tl4 + (size_t)blockIdx.z * Dv * Dv;
    const int n0 = blockIdx.x * 32, k0 = blockIdx.y * 32;
    const int tx = threadIdx.x & 31, ty = threadIdx.x >> 5;
    #pragma unroll
    for (int r = ty; r < 32; r += 8)
        t[r][tx] = W[(size_t)(k0 + r) * Dv + n0 + tx];
    __syncthreads();
    #pragma unroll
    for (int r = ty; r < 32; r += 8) {
        float v = t[tx][r];
        __nv_bfloat16 h = __float2bfloat16(v);
        th[(size_t)(n0 + r) * Dv + k0 + tx] = h;
        tl[(size_t)(n0 + r) * Dv + k0 + tx] = __float2bfloat16(v - __bfloat162float(h));
    }
}

// ================== mma.sync split-bf16 GEMM (R10, unchanged) ===============
#define NIT   32
#define PITCH 80
#define OFF_AH 0
#define OFF_AL 10240
#define OFF_BH 20480
#define OFF_BL 30720
#define STG    40960
#define SMEM_G (2 * STG)

#define GEMM_PROLOGUE_AND_LOOP(Ah_, Al_, Bh_, Bl_)                              \
    float acc[4][8][4];                                                         \
    _Pragma("unroll")                                                           \
    for (int i = 0; i < 4; i++)                                                 \
        _Pragma("unroll")                                                       \
        for (int j = 0; j < 8; j++) {                                           \
            acc[i][j][0] = 0.f; acc[i][j][1] = 0.f;                             \
            acc[i][j][2] = 0.f; acc[i][j][3] = 0.f;                             \
        }                                                                       \
    const int crow[4] = { tid >> 2, (tid + 128) >> 2, (tid + 256) >> 2,         \
                          (tid + 384) >> 2 };                                   \
    const int kc = tid & 3;                                                     \
    uint32_t soX[4]; size_t gaX[4], gbX[4];                                     \
    _Pragma("unroll")                                                           \
    for (int t = 0; t < 4; t++) {                                               \
        soX[t] = (uint32_t)(crow[t] * PITCH + kc * 16);                         \
        gaX[t] = (size_t)(bm + crow[t]) * Dv + kc * 8;                          \
        gbX[t] = (size_t)(bn + crow[t]) * Dv + kc * 8;                          \
    }                                                                           \
    const uint32_t aByte = (uint32_t)((wm * 64 + (lane & 15)) * PITCH           \
                                      + (lane >> 4) * 16);                      \
    const uint32_t bByte = (uint32_t)((wn * 64 + (lane >> 4) * 8 + (lane & 7))  \
                                      * PITCH + ((lane >> 3) & 1) * 16);        \
    {   /* prologue: stage 0 */                                                 \
        const uint32_t s = sb;                                                  \
        _Pragma("unroll")                                                       \
        for (int t = 0; t < 4; t++) {                                           \
            cpa16(s + OFF_AH + soX[t], Ah_ + gaX[t]);                           \
            cpa16(s + OFF_AL + soX[t], Al_ + gaX[t]);                           \
            cpa16(s + OFF_BH + soX[t], Bh_ + gbX[t]);                           \
            cpa16(s + OFF_BL + soX[t], Bl_ + gbX[t]);                           \
        }                                                                       \
        CP_COMMIT();                                                            \
    }                                                                           \
    _Pragma("unroll 1")                                                         \
    for (int it = 0; it < NIT; it++) {                                          \
        CP_WAIT0();                                                             \
        __syncthreads();                                                        \
        if (it + 1 < NIT) {                                                     \
            const int k0 = (it + 1) * 32;                                       \
            const uint32_t s = sb + ((it + 1) & 1) * STG;                       \
            _Pragma("unroll")                                                   \
            for (int t = 0; t < 4; t++) {                                       \
                cpa16(s + OFF_AH + soX[t], Ah_ + gaX[t] + k0);                  \
                cpa16(s + OFF_AL + soX[t], Al_ + gaX[t] + k0);                  \
                cpa16(s + OFF_BH + soX[t], Bh_ + gbX[t] + k0);                  \
                cpa16(s + OFF_BL + soX[t], Bl_ + gbX[t] + k0);                  \
            }                                                                   \
            CP_COMMIT();                                                        \
        }                                                                       \
        const uint32_t aB = sb + (it & 1) * STG + aByte;                        \
        const uint32_t bB = sb + (it & 1) * STG + bByte;                        \
        _Pragma("unroll")                                                       \
        for (int ks = 0; ks < 2; ks++) {                                        \
            uint32_t ahr[4][4], alr[4][4], bhr[4][4], blr[4][4];                \
            _Pragma("unroll")                                                   \
            for (int mt = 0; mt < 4; mt++) {                                    \
                ldsm4(ahr[mt], aB + OFF_AH + mt * (16 * PITCH) + ks * 32);      \
                ldsm4(alr[mt], aB + OFF_AL + mt * (16 * PITCH) + ks * 32);      \
            }                                                                   \
            _Pragma("unroll")                                                   \
            for (int p = 0; p < 4; p++) {                                       \
                ldsm4(bhr[p], bB + OFF_BH + p * (16 * PITCH) + ks * 32);        \
                ldsm4(blr[p], bB + OFF_BL + p * (16 * PITCH) + ks * 32);        \
            }                                                                   \
            _Pragma("unroll")                                                   \
            for (int mt = 0; mt < 4; mt++)                                      \
                _Pragma("unroll")                                               \
                for (int nt = 0; nt < 8; nt++) {                                \
                    const uint32_t* bh2 = &bhr[nt >> 1][(nt & 1) * 2];          \
                    const uint32_t* bl2 = &blr[nt >> 1][(nt & 1) * 2];          \
                    mma_bf16(acc[mt][nt], ahr[mt], bh2);                        \
                    mma_bf16(acc[mt][nt], ahr[mt], bl2);                        \
                    mma_bf16(acc[mt][nt], alr[mt], bh2);                        \
                }                                                               \
        }                                                                       \
    }

__global__ __launch_bounds__(128, 2) void gemm_proj(
    const __nv_bfloat16* __restrict__ Ah, const __nv_bfloat16* __restrict__ Al,
    const __nv_bfloat16* __restrict__ Wh, const __nv_bfloat16* __restrict__ Wl,
    ProjOut po)
{
    extern __shared__ char sm[];
    const uint32_t sb = smem_u32(sm);
    const int tid = threadIdx.x, lane = tid & 31, wid = tid >> 5;
    const int wm = wid >> 1, wn = wid & 1;
    const int bm = blockIdx.y * 128, bn = blockIdx.x * 128;
    const int z = blockIdx.z;
    const __nv_bfloat16* Bh_ = Wh + (size_t)z * Dv * Dv;
    const __nv_bfloat16* Bl_ = Wl + (size_t)z * Dv * Dv;
    const float* bias = po.bias[z];
    __nv_bfloat16* Oh = po.oh[z];
    __nv_bfloat16* Ol = po.ol[z];
    const float oscale = (z == 0) ? 0.125f : 1.0f;

    GEMM_PROLOGUE_AND_LOOP(Ah, Al, Bh_, Bl_)

    const int g = lane >> 2, tg = lane & 3;
    #pragma unroll
    for (int nt = 0; nt < 8; nt++) {
        const int n0 = bn + wn * 64 + nt * 8 + tg * 2;
        const float b0 = __ldg(bias + n0), b1 = __ldg(bias + n0 + 1);
        const int h = n0 >> 6, d = n0 & 63;
        #pragma unroll
        for (int mt = 0; mt < 4; mt++) {
            const int mrow0 = bm + wm * 64 + mt * 16 + g;
            float v0 = fmaxf(acc[mt][nt][0] + b0, 0.f) * oscale;
            float v1 = fmaxf(acc[mt][nt][1] + b1, 0.f) * oscale;
            float v2 = fmaxf(acc[mt][nt][2] + b0, 0.f) * oscale;
            float v3 = fmaxf(acc[mt][nt][3] + b1, 0.f) * oscale;
            const size_t i0 = (((size_t)(mrow0 >> 11) * 16 + h) * 2048
                              + (mrow0 & 2047)) * 64 + d;
            const size_t i2 = i0 + 8 * 64;
            *(uint32_t*)(Oh + i0) = packf_hi(v0, v1);
            *(uint32_t*)(Ol + i0) = packf_lo(v0, v1);
            *(uint32_t*)(Oh + i2) = packf_hi(v2, v3);
            *(uint32_t*)(Ol + i2) = packf_lo(v2, v3);
        }
    }
}

__global__ __launch_bounds__(128, 2) void gemm_out(
    const __nv_bfloat16* __restrict__ Ah, const __nv_bfloat16* __restrict__ Al,
    const __nv_bfloat16* __restrict__ Bh_, const __nv_bfloat16* __restrict__ Bl_,
    const float* __restrict__ bias, float* __restrict__ C)
{
    extern __shared__ char sm[];
    const uint32_t sb = smem_u32(sm);
    const int tid = threadIdx.x, lane = tid & 31, wid = tid >> 5;
    const int wm = wid >> 1, wn = wid & 1;
    const int bm = blockIdx.y * 128, bn = blockIdx.x * 128;

    GEMM_PROLOGUE_AND_LOOP(Ah, Al, Bh_, Bl_)

    const int g = lane >> 2, tg = lane & 3;
    #pragma unroll
    for (int nt = 0; nt < 8; nt++) {
        const int n0 = bn + wn * 64 + nt * 8 + tg * 2;
        const float b0 = __ldg(bias + n0), b1 = __ldg(bias + n0 + 1);
        #pragma unroll
        for (int mt = 0; mt < 4; mt++) {
            const int mrow0 = bm + wm * 64 + mt * 16 + g;
            float2 o;
            o.x = fmaxf(acc[mt][nt][0] + b0, 0.f);
            o.y = fmaxf(acc[mt][nt][1] + b1, 0.f);
            *(float2*)(C + (size_t)mrow0 * Dv + n0) = o;
            o.x = fmaxf(acc[mt][nt][2] + b0, 0.f);
            o.y = fmaxf(acc[mt][nt][3] + b1, 0.f);
            *(float2*)(C + (size_t)(mrow0 + 8) * Dv + n0) = o;
        }
    }
}

// ================== tensor-core flash attention =============================
// 128 q rows/CTA, 2-term PV, exp-skip, single barrier per tile, 3-stage ring.
// NEW: strictly-future tiles use 1-term QK (Qh.Kh only) — they only feed the
// running max, and an m perturbation cancels in ctx/(l+eps) except on
// eps-dominated (negligible-output) rows.
#define AP   144
#define AST  36864
#define A_KH 0
#define A_KL 9216
#define A_VH 18432
#define A_VL 27648
#define SMEM_A (3 * AST)          // 110592

__global__ __launch_bounds__(256, 2) void attn_mma(
    const __nv_bfloat16* __restrict__ Qh, const __nv_bfloat16* __restrict__ Ql,
    const __nv_bfloat16* __restrict__ Kh, const __nv_bfloat16* __restrict__ Kl,
    const __nv_bfloat16* __restrict__ Vh, const __nv_bfloat16* __restrict__ Vl,
    __nv_bfloat16* __restrict__ Chi, __nv_bfloat16* __restrict__ Clo)
{
    extern __shared__ char sm[];
    const uint32_t sb = smem_u32(sm);
    const int tid = threadIdx.x, lane = tid & 31, wid = tid >> 5;
    const int bx = blockIdx.x, bh = blockIdx.y;
    const size_t hbase = (size_t)bh * (Sv * HDv);
    const int g = lane >> 2, tg = lane & 3;

    // ---- stage Q into smem (stage0 area), then ldmatrix to regs ----
    #pragma unroll
    for (int c = tid; c < 1024; c += 256) {
        const int row = c >> 3, col = (c & 7) * 16;
        const size_t gsrc = hbase + (size_t)(bx * 128 + row) * 64 + (c & 7) * 8;
        cpa16(sb + row * AP + col, Qh + gsrc);
        cpa16(sb + 18432 + row * AP + col, Ql + gsrc);
    }
    CP_COMMIT(); CP_WAIT0();
    __syncthreads();

    uint32_t qh[4][4], ql[4][4];
    {
        const uint32_t aAddr = sb + (wid * 16 + (lane & 15)) * AP + (lane >> 4) * 16;
        #pragma unroll
        for (int kb = 0; kb < 4; kb++) {
            ldsm4(qh[kb], aAddr + kb * 32);
            ldsm4(ql[kb], aAddr + 18432 + kb * 32);
        }
    }
    __syncthreads();   // all warps consumed Q before tile-0 prefetch overwrites

    float m0 = -1e30f, m1 = -1e30f, l0 = 0.f, l1 = 0.f;
    float ctx[8][4];
    #pragma unroll
    for (int i = 0; i < 8; i++)
        #pragma unroll
        for (int j = 0; j < 4; j++) ctx[i][j] = 0.f;

    const int qg0 = bx * 128 + wid * 16 + g;
    const int qg8 = qg0 + 8;
    const int lastPV = 2 * bx + 1;

    // prologue: prefetch tiles 0 and 1 (both always causal-full: lastPV >= 1)
    #pragma unroll
    for (int ps = 0; ps < 2; ps++) {
        const uint32_t s = sb + ps * AST;
        const size_t rb = hbase + (size_t)ps * 64 * 64;
        #pragma unroll
        for (int c = tid; c < 512; c += 256) {
            const int row = c >> 3;
            const uint32_t col = (uint32_t)((c & 7) * 16);
            const size_t gs = rb + (size_t)row * 64 + (c & 7) * 8;
            cpa16(s + A_KH + row * AP + col, Kh + gs);
            cpa16(s + A_KL + row * AP + col, Kl + gs);
            cpa16(s + A_VH + row * AP + col, Vh + gs);
            cpa16(s + A_VL + row * AP + col, Vl + gs);
        }
        CP_COMMIT();
    }

    const uint32_t kPat = (uint32_t)(((lane >> 4) * 8 + (lane & 7)) * AP
                                     + ((lane >> 3) & 1) * 16);
    const uint32_t vPat = (uint32_t)(((lane & 7) + ((lane >> 3) & 1) * 8) * AP
                                     + (lane >> 4) * 16);

    int stage = 0, pstage = 2;
    #pragma unroll 1
    for (int kt = 0; kt < 32; kt++) {
        if (kt < 31) { CP_WAIT1(); } else { CP_WAIT0(); }
        __syncthreads();   // orders compute(kt-1) before pstage overwrite below

        // prefetch tile kt+2 into the stage consumed at iter kt-1
        if (kt + 2 < 32) {
            const int nt_ = kt + 2;
            const uint32_t s = sb + pstage * AST;
            const size_t rb = hbase + (size_t)nt_ * 64 * 64;
            const bool full = (nt_ <= lastPV);
            #pragma unroll
            for (int c = tid; c < 512; c += 256) {
                const int row = c >> 3;
                const uint32_t col = (uint32_t)((c & 7) * 16);
                const size_t gs = rb + (size_t)row * 64 + (c & 7) * 8;
                cpa16(s + A_KH + row * AP + col, Kh + gs);
                if (full) {
                    cpa16(s + A_KL + row * AP + col, Kl + gs);
                    cpa16(s + A_VH + row * AP + col, Vh + gs);
                    cpa16(s + A_VL + row * AP + col, Vl + gs);
                }
            }
            CP_COMMIT();
        }

        const uint32_t base = sb + stage * AST;
        const bool fut = (kt > lastPV);

        float S[8][4];
        #pragma unroll
        for (int i = 0; i < 8; i++)
            #pragma unroll
            for (int j = 0; j < 4; j++) S[i][j] = 0.f;

        const uint32_t kAddr = base + kPat;
        #pragma unroll
        for (int nb = 0; nb < 4; nb++) {
            #pragma unroll
            for (int kb = 0; kb < 4; kb++) {
                uint32_t rh[4];
                ldsm4(rh, kAddr + A_KH + nb * (16 * AP) + kb * 32);
                mma_bf16(S[2 * nb], qh[kb], rh + 0);
                mma_bf16(S[2 * nb + 1], qh[kb], rh + 2);
                if (!fut) {
                    mma_bf16(S[2 * nb], ql[kb], rh + 0);
                    mma_bf16(S[2 * nb + 1], ql[kb], rh + 2);
                    uint32_t rl[4];
                    ldsm4(rl, kAddr + A_KL + nb * (16 * AP) + kb * 32);
                    mma_bf16(S[2 * nb], qh[kb], rl + 0);
                    mma_bf16(S[2 * nb + 1], qh[kb], rl + 2);
                }
            }
        }

        float rm0 = -1e30f, rm1 = -1e30f;
        #pragma unroll
        for (int i = 0; i < 8; i++) {
            rm0 = fmaxf(rm0, fmaxf(S[i][0], S[i][1]));
            rm1 = fmaxf(rm1, fmaxf(S[i][2], S[i][3]));
        }
        rm0 = fmaxf(rm0, __shfl_xor_sync(0xffffffffu, rm0, 1));
        rm0 = fmaxf(rm0, __shfl_xor_sync(0xffffffffu, rm0, 2));
        rm1 = fmaxf(rm1, __shfl_xor_sync(0xffffffffu, rm1, 1));
        rm1 = fmaxf(rm1, __shfl_xor_sync(0xffffffffu, rm1, 2));
        if (rm0 > m0 || rm1 > m1) {
            const float M0 = fmaxf(m0, rm0);
            const float M1 = fmaxf(m1, rm1);
            const float f0 = __expf(m0 - M0);
            const float f1 = __expf(m1 - M1);
            l0 *= f0; l1 *= f1;
            #pragma unroll
            for (int i = 0; i < 8; i++) {
                ctx[i][0] *= f0; ctx[i][1] *= f0;
                ctx[i][2] *= f1; ctx[i][3] *= f1;
            }
            m0 = M0; m1 = M1;
        }

        if (!fut) {
            uint32_t ph[8][2];
            const int jb = kt * 64 + 2 * tg;
            #pragma unroll
            for (int nt = 0; nt < 8; nt++) {
                const int j0 = jb + nt * 8;
                const float p0 = (j0 <= qg0) ? __expf(S[nt][0] - m0) : 0.f;
                const float p1 = (j0 + 1 <= qg0) ? __expf(S[nt][1] - m0) : 0.f;
                const float p2 = (j0 <= qg8) ? __expf(S[nt][2] - m1) : 0.f;
                const float p3 = (j0 + 1 <= qg8) ? __expf(S[nt][3] - m1) : 0.f;
                l0 += p0 + p1; l1 += p2 + p3;
                ph[nt][0] = packf_hi(p0, p1);
                ph[nt][1] = packf_hi(p2, p3);
            }
            const uint32_t vAddr = base + vPat;
            #pragma unroll
            for (int kk = 0; kk < 4; kk++) {
                uint32_t Ahh[4] = { ph[2 * kk][0], ph[2 * kk][1],
                                    ph[2 * kk + 1][0], ph[2 * kk + 1][1] };
                #pragma unroll
                for (int db = 0; db < 4; db++) {
                    uint32_t vh4[4], vl4[4];
                    const uint32_t va = vAddr + kk * (16 * AP) + db * 32;
                    ldsm4t(vh4, va + A_VH);
                    ldsm4t(vl4, va + A_VL);
                    mma_bf16(ctx[2 * db], Ahh, vh4 + 0);
                    mma_bf16(ctx[2 * db + 1], Ahh, vh4 + 2);
                    mma_bf16(ctx[2 * db], Ahh, vl4 + 0);
                    mma_bf16(ctx[2 * db + 1], Ahh, vl4 + 2);
                }
            }
        }
        stage = (stage + 1 == 3) ? 0 : stage + 1;
        pstage = (pstage + 1 == 3) ? 0 : pstage + 1;
    }

    l0 += __shfl_xor_sync(0xffffffffu, l0, 1);
    l0 += __shfl_xor_sync(0xffffffffu, l0, 2);
    l1 += __shfl_xor_sync(0xffffffffu, l1, 1);
    l1 += __shfl_xor_sync(0xffffffffu, l1, 2);
    const float inv0 = 1.0f / (l0 + EPSv);
    const float inv1 = 1.0f / (l1 + EPSv);

    const int b = bh >> 4, h = bh & 15;
    const size_t o0 = ((size_t)(b * Sv + qg0)) * Dv + h * 64;
    const size_t o8 = ((size_t)(b * Sv + qg8)) * Dv + h * 64;
    #pragma unroll
    for (int nt = 0; nt < 8; nt++) {
        const int d0 = nt * 8 + tg * 2;
        const float v0 = ctx[nt][0] * inv0, v1 = ctx[nt][1] * inv0;
        const float v2 = ctx[nt][2] * inv1, v3 = ctx[nt][3] * inv1;
        *(uint32_t*)(Chi + o0 + d0) = packf_hi(v0, v1);
        *(uint32_t*)(Clo + o0 + d0) = packf_lo(v0, v1);
        *(uint32_t*)(Chi + o8 + d0) = packf_hi(v2, v3);
        *(uint32_t*)(Clo + o8 + d0) = packf_lo(v2, v3);
    }
}

// ---------------- launch -----------------------------------------------------
extern "C" void kernel_launch(void* const* d_in, const int* in_sizes, int n_in,
                              void* d_out, int out_size)
{
    const float* x  = (const float*)d_in[0];
    const float* Wq = (const float*)d_in[1];
    const float* bq = (const float*)d_in[2];
    const float* Wk = (const float*)d_in[3];
    const float* bk = (const float*)d_in[4];
    const float* Wv = (const float*)d_in[5];
    const float* bv = (const float*)d_in[6];
    const float* Wo = (const float*)d_in[7];
    const float* bo = (const float*)d_in[8];
    float* out = (float*)d_out;

    __nv_bfloat16 *xhi, *xlo, *wh, *wl;
    __nv_bfloat16 *qhi, *qlo, *khi, *klo, *vhi, *vlo, *chi, *clo;
    cudaGetSymbolAddress((void**)&xhi, g_xhi);
    cudaGetSymbolAddress((void**)&xlo, g_xlo);
    cudaGetSymbolAddress((void**)&wh,  g_wh);
    cudaGetSymbolAddress((void**)&wl,  g_wl);
    cudaGetSymbolAddress((void**)&qhi, g_qhi);
    cudaGetSymbolAddress((void**)&qlo, g_qlo);
    cudaGetSymbolAddress((void**)&khi, g_khi);
    cudaGetSymbolAddress((void**)&klo, g_klo);
    cudaGetSymbolAddress((void**)&vhi, g_vhi);
    cudaGetSymbolAddress((void**)&vlo, g_vlo);
    cudaGetSymbolAddress((void**)&chi, g_chi);
    cudaGetSymbolAddress((void**)&clo, g_clo);

    cudaFuncSetAttribute(gemm_proj, cudaFuncAttributeMaxDynamicSharedMemorySize, SMEM_G);
    cudaFuncSetAttribute(gemm_out, cudaFuncAttributeMaxDynamicSharedMemorySize, SMEM_G);
    cudaFuncSetAttribute(attn_mma, cudaFuncAttributeMaxDynamicSharedMemorySize, SMEM_A);

    const int n4 = Mv * Dv / 4;
    split_rm<<<n4 / 256, 256>>>((const float4*)x, (__nv_bfloat162*)xhi,
                                (__nv_bfloat162*)xlo, n4);

    WSrc ws;
    ws.w[0] = Wq; ws.w[1] = Wk; ws.w[2] = Wv; ws.w[3] = Wo;
    dim3 tgrid(Dv / 32, Dv / 32, 4);
    tsplit4<<<tgrid, 256>>>(ws, wh, wl);

    ProjOut po;
    po.bias[0] = bq; po.bias[1] = bk; po.bias[2] = bv;
    po.oh[0] = qhi; po.oh[1] = khi; po.oh[2] = vhi;
    po.ol[0] = qlo; po.ol[1] = klo; po.ol[2] = vlo;

    dim3 pgrid(Dv / 128, Mv / 128, 3);   // fused Q/K/V
    gemm_proj<<<pgrid, 128, SMEM_G>>>(xhi, xlo, wh, wl, po);

    dim3 agrid(Sv / 128, Bv * Hv);       // (16, 64)
    attn_mma<<<agrid, 256, SMEM_A>>>(qhi, qlo, khi, klo, vhi, vlo, chi, clo);

    dim3 ggrid(Dv / 128, Mv / 128);
    gemm_out<<<ggrid, 128, SMEM_G>>>(chi, clo, wh + 3 * (size_t)Dv * Dv,
                                     wl + 3 * (size_t)Dv * Dv, bo, out);
}

// round 17
// speedup vs baseline: 1.6344x; 1.0506x over previous
#include <cuda_runtime.h>
#include <cuda_bf16.h>
#include <math.h>
#include <stdint.h>

#define Bv 4
#define Sv 2048
#define Dv 1024
#define Hv 16
#define HDv 64
#define Mv (Bv * Sv)          // 8192
#define EPSv 1e-7f

// ---------------- scratch (static device memory; no allocs) ----------------
__device__ __nv_bfloat16 g_xhi[Mv * Dv], g_xlo[Mv * Dv];
__device__ __nv_bfloat16 g_wh[4][Dv * Dv], g_wl[4][Dv * Dv];  // transposed [N][K]
__device__ __nv_bfloat16 g_qhi[Mv * Dv], g_qlo[Mv * Dv];
__device__ __nv_bfloat16 g_khi[Mv * Dv], g_klo[Mv * Dv];
__device__ __nv_bfloat16 g_vhi[Mv * Dv], g_vlo[Mv * Dv];
__device__ __nv_bfloat16 g_chi[Mv * Dv], g_clo[Mv * Dv];

struct ProjOut {
    const float* bias[3];
    __nv_bfloat16* oh[3];
    __nv_bfloat16* ol[3];
};
struct WSrc { const float* w[4]; };

// ======================= helpers ===========================================
__device__ __forceinline__ uint32_t smem_u32(const void* p) {
    uint32_t a;
    asm("{ .reg .u64 t; cvta.to.shared.u64 t, %1; cvt.u32.u64 %0, t; }"
        : "=r"(a) : "l"(p));
    return a;
}

__device__ __forceinline__ void cpa16(uint32_t d, const void* g) {
    asm volatile("cp.async.cg.shared.global [%0], [%1], 16;" :: "r"(d), "l"(g));
}
#define CP_COMMIT() asm volatile("cp.async.commit_group;" ::: "memory")
#define CP_WAIT0()  asm volatile("cp.async.wait_group 0;" ::: "memory")
#define CP_WAIT1()  asm volatile("cp.async.wait_group 1;" ::: "memory")

__device__ __forceinline__ void ldsm4(uint32_t* r, uint32_t a) {
    asm volatile("ldmatrix.sync.aligned.m8n8.x4.shared.b16 {%0,%1,%2,%3}, [%4];"
        : "=r"(r[0]), "=r"(r[1]), "=r"(r[2]), "=r"(r[3]) : "r"(a));
}
__device__ __forceinline__ void ldsm4t(uint32_t* r, uint32_t a) {
    asm volatile("ldmatrix.sync.aligned.m8n8.x4.trans.shared.b16 {%0,%1,%2,%3}, [%4];"
        : "=r"(r[0]), "=r"(r[1]), "=r"(r[2]), "=r"(r[3]) : "r"(a));
}

__device__ __forceinline__ void mma_bf16(float* d, const uint32_t* a, const uint32_t* b) {
    asm volatile(
        "mma.sync.aligned.m16n8k16.row.col.f32.bf16.bf16.f32 "
        "{%0,%1,%2,%3}, {%4,%5,%6,%7}, {%8,%9}, {%0,%1,%2,%3};"
        : "+f"(d[0]), "+f"(d[1]), "+f"(d[2]), "+f"(d[3])
        : "r"(a[0]), "r"(a[1]), "r"(a[2]), "r"(a[3]), "r"(b[0]), "r"(b[1]));
}

// packed bf16x2 convert (rn per half, one instruction)
__device__ __forceinline__ uint32_t packf_hi(float a, float b) {
    uint32_t r;
    asm("cvt.rn.bf16x2.f32 %0, %2, %1;" : "=r"(r) : "f"(a), "f"(b));
    return r;
}
__device__ __forceinline__ uint32_t packf_lo(float a, float b) {
    const float ra = a - __bfloat162float(__float2bfloat16(a));
    const float rb = b - __bfloat162float(__float2bfloat16(b));
    uint32_t r;
    asm("cvt.rn.bf16x2.f32 %0, %2, %1;" : "=r"(r) : "f"(ra), "f"(rb));
    return r;
}

// ---------------- convert kernels ------------------------------------------
__global__ __launch_bounds__(256) void split_rm(
    const float4* __restrict__ src, __nv_bfloat162* __restrict__ hi,
    __nv_bfloat162* __restrict__ lo, int n4)
{
    int i = blockIdx.x * 256 + threadIdx.x;
    if (i >= n4) return;
    float4 v = src[i];
    uint32_t h01 = packf_hi(v.x, v.y), h23 = packf_hi(v.z, v.w);
    uint32_t l01 = packf_lo(v.x, v.y), l23 = packf_lo(v.z, v.w);
    ((uint32_t*)hi)[2 * i] = h01; ((uint32_t*)hi)[2 * i + 1] = h23;
    ((uint32_t*)lo)[2 * i] = l01; ((uint32_t*)lo)[2 * i + 1] = l23;
}

// all 4 weights: [K][N] row-major -> transposed bf16 hi/lo [N][K], grid.z picks W
__global__ __launch_bounds__(256) void tsplit4(
    WSrc ws, __nv_bfloat16* __restrict__ th4, __nv_bfloat16* __restrict__ tl4)
{
    __shared__ float t[32][33];
    const float* W = ws.w[blockIdx.z];
    __nv_bfloat16* th = th4 + (size_t)blockIdx.z * Dv * Dv;
    __nv_bfloat16* tl = tl4 + (size_t)blockIdx.z * Dv * Dv;
    const int n0 = blockIdx.x * 32, k0 = blockIdx.y * 32;
    const int tx = threadIdx.x & 31, ty = threadIdx.x >> 5;
    #pragma unroll
    for (int r = ty; r < 32; r += 8)
        t[r][tx] = W[(size_t)(k0 + r) * Dv + n0 + tx];
    __syncthreads();
    #pragma unroll
    for (int r = ty; r < 32; r += 8) {
        float v = t[tx][r];
        __nv_bfloat16 h = __float2bfloat16(v);
        th[(size_t)(n0 + r) * Dv + k0 + tx] = h;
        tl[(size_t)(n0 + r) * Dv + k0 + tx] = __float2bfloat16(v - __bfloat162float(h));
    }
}

// ================== mma.sync split-bf16 GEMM (R10, unchanged) ===============
#define NIT   32
#define PITCH 80
#define OFF_AH 0
#define OFF_AL 10240
#define OFF_BH 20480
#define OFF_BL 30720
#define STG    40960
#define SMEM_G (2 * STG)

#define GEMM_PROLOGUE_AND_LOOP(Ah_, Al_, Bh_, Bl_)                              \
    float acc[4][8][4];                                                         \
    _Pragma("unroll")                                                           \
    for (int i = 0; i < 4; i++)                                                 \
        _Pragma("unroll")                                                       \
        for (int j = 0; j < 8; j++) {                                           \
            acc[i][j][0] = 0.f; acc[i][j][1] = 0.f;                             \
            acc[i][j][2] = 0.f; acc[i][j][3] = 0.f;                             \
        }                                                                       \
    const int crow[4] = { tid >> 2, (tid + 128) >> 2, (tid + 256) >> 2,         \
                          (tid + 384) >> 2 };                                   \
    const int kc = tid & 3;                                                     \
    uint32_t soX[4]; size_t gaX[4], gbX[4];                                     \
    _Pragma("unroll")                                                           \
    for (int t = 0; t < 4; t++) {                                               \
        soX[t] = (uint32_t)(crow[t] * PITCH + kc * 16);                         \
        gaX[t] = (size_t)(bm + crow[t]) * Dv + kc * 8;                          \
        gbX[t] = (size_t)(bn + crow[t]) * Dv + kc * 8;                          \
    }                                                                           \
    const uint32_t aByte = (uint32_t)((wm * 64 + (lane & 15)) * PITCH           \
                                      + (lane >> 4) * 16);                      \
    const uint32_t bByte = (uint32_t)((wn * 64 + (lane >> 4) * 8 + (lane & 7))  \
                                      * PITCH + ((lane >> 3) & 1) * 16);        \
    {   /* prologue: stage 0 */                                                 \
        const uint32_t s = sb;                                                  \
        _Pragma("unroll")                                                       \
        for (int t = 0; t < 4; t++) {                                           \
            cpa16(s + OFF_AH + soX[t], Ah_ + gaX[t]);                           \
            cpa16(s + OFF_AL + soX[t], Al_ + gaX[t]);                           \
            cpa16(s + OFF_BH + soX[t], Bh_ + gbX[t]);                           \
            cpa16(s + OFF_BL + soX[t], Bl_ + gbX[t]);                           \
        }                                                                       \
        CP_COMMIT();                                                            \
    }                                                                           \
    _Pragma("unroll 1")                                                         \
    for (int it = 0; it < NIT; it++) {                                          \
        CP_WAIT0();                                                             \
        __syncthreads();                                                        \
        if (it + 1 < NIT) {                                                     \
            const int k0 = (it + 1) * 32;                                       \
            const uint32_t s = sb + ((it + 1) & 1) * STG;                       \
            _Pragma("unroll")                                                   \
            for (int t = 0; t < 4; t++) {                                       \
                cpa16(s + OFF_AH + soX[t], Ah_ + gaX[t] + k0);                  \
                cpa16(s + OFF_AL + soX[t], Al_ + gaX[t] + k0);                  \
                cpa16(s + OFF_BH + soX[t], Bh_ + gbX[t] + k0);                  \
                cpa16(s + OFF_BL + soX[t], Bl_ + gbX[t] + k0);                  \
            }                                                                   \
            CP_COMMIT();                                                        \
        }                                                                       \
        const uint32_t aB = sb + (it & 1) * STG + aByte;                        \
        const uint32_t bB = sb + (it & 1) * STG + bByte;                        \
        _Pragma("unroll")                                                       \
        for (int ks = 0; ks < 2; ks++) {                                        \
            uint32_t ahr[4][4], alr[4][4], bhr[4][4], blr[4][4];                \
            _Pragma("unroll")                                                   \
            for (int mt = 0; mt < 4; mt++) {                                    \
                ldsm4(ahr[mt], aB + OFF_AH + mt * (16 * PITCH) + ks * 32);      \
                ldsm4(alr[mt], aB + OFF_AL + mt * (16 * PITCH) + ks * 32);      \
            }                                                                   \
            _Pragma("unroll")                                                   \
            for (int p = 0; p < 4; p++) {                                       \
                ldsm4(bhr[p], bB + OFF_BH + p * (16 * PITCH) + ks * 32);        \
                ldsm4(blr[p], bB + OFF_BL + p * (16 * PITCH) + ks * 32);        \
            }                                                                   \
            _Pragma("unroll")                                                   \
            for (int mt = 0; mt < 4; mt++)                                      \
                _Pragma("unroll")                                               \
                for (int nt = 0; nt < 8; nt++) {                                \
                    const uint32_t* bh2 = &bhr[nt >> 1][(nt & 1) * 2];          \
                    const uint32_t* bl2 = &blr[nt >> 1][(nt & 1) * 2];          \
                    mma_bf16(acc[mt][nt], ahr[mt], bh2);                        \
                    mma_bf16(acc[mt][nt], ahr[mt], bl2);                        \
                    mma_bf16(acc[mt][nt], alr[mt], bh2);                        \
                }                                                               \
        }                                                                       \
    }

__global__ __launch_bounds__(128, 2) void gemm_proj(
    const __nv_bfloat16* __restrict__ Ah, const __nv_bfloat16* __restrict__ Al,
    const __nv_bfloat16* __restrict__ Wh, const __nv_bfloat16* __restrict__ Wl,
    ProjOut po)
{
    extern __shared__ char sm[];
    const uint32_t sb = smem_u32(sm);
    const int tid = threadIdx.x, lane = tid & 31, wid = tid >> 5;
    const int wm = wid >> 1, wn = wid & 1;
    const int bm = blockIdx.y * 128, bn = blockIdx.x * 128;
    const int z = blockIdx.z;
    const __nv_bfloat16* Bh_ = Wh + (size_t)z * Dv * Dv;
    const __nv_bfloat16* Bl_ = Wl + (size_t)z * Dv * Dv;
    const float* bias = po.bias[z];
    __nv_bfloat16* Oh = po.oh[z];
    __nv_bfloat16* Ol = po.ol[z];
    const float oscale = (z == 0) ? 0.125f : 1.0f;

    GEMM_PROLOGUE_AND_LOOP(Ah, Al, Bh_, Bl_)

    const int g = lane >> 2, tg = lane & 3;
    #pragma unroll
    for (int nt = 0; nt < 8; nt++) {
        const int n0 = bn + wn * 64 + nt * 8 + tg * 2;
        const float b0 = __ldg(bias + n0), b1 = __ldg(bias + n0 + 1);
        const int h = n0 >> 6, d = n0 & 63;
        #pragma unroll
        for (int mt = 0; mt < 4; mt++) {
            const int mrow0 = bm + wm * 64 + mt * 16 + g;
            float v0 = fmaxf(acc[mt][nt][0] + b0, 0.f) * oscale;
            float v1 = fmaxf(acc[mt][nt][1] + b1, 0.f) * oscale;
            float v2 = fmaxf(acc[mt][nt][2] + b0, 0.f) * oscale;
            float v3 = fmaxf(acc[mt][nt][3] + b1, 0.f) * oscale;
            const size_t i0 = (((size_t)(mrow0 >> 11) * 16 + h) * 2048
                              + (mrow0 & 2047)) * 64 + d;
            const size_t i2 = i0 + 8 * 64;
            *(uint32_t*)(Oh + i0) = packf_hi(v0, v1);
            *(uint32_t*)(Ol + i0) = packf_lo(v0, v1);
            *(uint32_t*)(Oh + i2) = packf_hi(v2, v3);
            *(uint32_t*)(Ol + i2) = packf_lo(v2, v3);
        }
    }
}

__global__ __launch_bounds__(128, 2) void gemm_out(
    const __nv_bfloat16* __restrict__ Ah, const __nv_bfloat16* __restrict__ Al,
    const __nv_bfloat16* __restrict__ Bh_, const __nv_bfloat16* __restrict__ Bl_,
    const float* __restrict__ bias, float* __restrict__ C)
{
    extern __shared__ char sm[];
    const uint32_t sb = smem_u32(sm);
    const int tid = threadIdx.x, lane = tid & 31, wid = tid >> 5;
    const int wm = wid >> 1, wn = wid & 1;
    const int bm = blockIdx.y * 128, bn = blockIdx.x * 128;

    GEMM_PROLOGUE_AND_LOOP(Ah, Al, Bh_, Bl_)

    const int g = lane >> 2, tg = lane & 3;
    #pragma unroll
    for (int nt = 0; nt < 8; nt++) {
        const int n0 = bn + wn * 64 + nt * 8 + tg * 2;
        const float b0 = __ldg(bias + n0), b1 = __ldg(bias + n0 + 1);
        #pragma unroll
        for (int mt = 0; mt < 4; mt++) {
            const int mrow0 = bm + wm * 64 + mt * 16 + g;
            float2 o;
            o.x = fmaxf(acc[mt][nt][0] + b0, 0.f);
            o.y = fmaxf(acc[mt][nt][1] + b1, 0.f);
            *(float2*)(C + (size_t)mrow0 * Dv + n0) = o;
            o.x = fmaxf(acc[mt][nt][2] + b0, 0.f);
            o.y = fmaxf(acc[mt][nt][3] + b1, 0.f);
            *(float2*)(C + (size_t)(mrow0 + 8) * Dv + n0) = o;
        }
    }
}

// ================== tensor-core flash attention =============================
// 128 q rows/CTA, exp-skip, single barrier per tile, 3-stage ring.
// Future tiles: 1-term QK.  NEW: PV is 1-term (Ph.Vh only; Vl never loaded) —
// symmetric to the R9 Pl-drop which measured +1.8e-4 rel_err.
#define AP   144
#define AST  27648                // 3 planes * 64*144 (KH, KL, VH)
#define A_KH 0
#define A_KL 9216
#define A_VH 18432
#define SMEM_A (3 * AST)          // 82944

__global__ __launch_bounds__(256, 2) void attn_mma(
    const __nv_bfloat16* __restrict__ Qh, const __nv_bfloat16* __restrict__ Ql,
    const __nv_bfloat16* __restrict__ Kh, const __nv_bfloat16* __restrict__ Kl,
    const __nv_bfloat16* __restrict__ Vh, const __nv_bfloat16* __restrict__ Vl,
    __nv_bfloat16* __restrict__ Chi, __nv_bfloat16* __restrict__ Clo)
{
    extern __shared__ char sm[];
    const uint32_t sb = smem_u32(sm);
    const int tid = threadIdx.x, lane = tid & 31, wid = tid >> 5;
    const int bx = blockIdx.x, bh = blockIdx.y;
    const size_t hbase = (size_t)bh * (Sv * HDv);
    const int g = lane >> 2, tg = lane & 3;

    // ---- stage Q into smem (stage0+1 area), then ldmatrix to regs ----
    #pragma unroll
    for (int c = tid; c < 1024; c += 256) {
        const int row = c >> 3, col = (c & 7) * 16;
        const size_t gsrc = hbase + (size_t)(bx * 128 + row) * 64 + (c & 7) * 8;
        cpa16(sb + row * AP + col, Qh + gsrc);
        cpa16(sb + 18432 + row * AP + col, Ql + gsrc);
    }
    CP_COMMIT(); CP_WAIT0();
    __syncthreads();

    uint32_t qh[4][4], ql[4][4];
    {
        const uint32_t aAddr = sb + (wid * 16 + (lane & 15)) * AP + (lane >> 4) * 16;
        #pragma unroll
        for (int kb = 0; kb < 4; kb++) {
            ldsm4(qh[kb], aAddr + kb * 32);
            ldsm4(ql[kb], aAddr + 18432 + kb * 32);
        }
    }
    __syncthreads();   // all warps consumed Q before tile-0 prefetch overwrites

    float m0 = -1e30f, m1 = -1e30f, l0 = 0.f, l1 = 0.f;
    float ctx[8][4];
    #pragma unroll
    for (int i = 0; i < 8; i++)
        #pragma unroll
        for (int j = 0; j < 4; j++) ctx[i][j] = 0.f;

    const int qg0 = bx * 128 + wid * 16 + g;
    const int qg8 = qg0 + 8;
    const int lastPV = 2 * bx + 1;

    // prologue: prefetch tiles 0 and 1 (both always causal-full: lastPV >= 1)
    #pragma unroll
    for (int ps = 0; ps < 2; ps++) {
        const uint32_t s = sb + ps * AST;
        const size_t rb = hbase + (size_t)ps * 64 * 64;
        #pragma unroll
        for (int c = tid; c < 512; c += 256) {
            const int row = c >> 3;
            const uint32_t col = (uint32_t)((c & 7) * 16);
            const size_t gs = rb + (size_t)row * 64 + (c & 7) * 8;
            cpa16(s + A_KH + row * AP + col, Kh + gs);
            cpa16(s + A_KL + row * AP + col, Kl + gs);
            cpa16(s + A_VH + row * AP + col, Vh + gs);
        }
        CP_COMMIT();
    }

    const uint32_t kPat = (uint32_t)(((lane >> 4) * 8 + (lane & 7)) * AP
                                     + ((lane >> 3) & 1) * 16);
    const uint32_t vPat = (uint32_t)(((lane & 7) + ((lane >> 3) & 1) * 8) * AP
                                     + (lane >> 4) * 16);

    int stage = 0, pstage = 2;
    #pragma unroll 1
    for (int kt = 0; kt < 32; kt++) {
        if (kt < 31) { CP_WAIT1(); } else { CP_WAIT0(); }
        __syncthreads();   // orders compute(kt-1) before pstage overwrite below

        // prefetch tile kt+2 into the stage consumed at iter kt-1
        if (kt + 2 < 32) {
            const int nt_ = kt + 2;
            const uint32_t s = sb + pstage * AST;
            const size_t rb = hbase + (size_t)nt_ * 64 * 64;
            const bool full = (nt_ <= lastPV);
            #pragma unroll
            for (int c = tid; c < 512; c += 256) {
                const int row = c >> 3;
                const uint32_t col = (uint32_t)((c & 7) * 16);
                const size_t gs = rb + (size_t)row * 64 + (c & 7) * 8;
                cpa16(s + A_KH + row * AP + col, Kh + gs);
                if (full) {
                    cpa16(s + A_KL + row * AP + col, Kl + gs);
                    cpa16(s + A_VH + row * AP + col, Vh + gs);
                }
            }
            CP_COMMIT();
        }

        const uint32_t base = sb + stage * AST;
        const bool fut = (kt > lastPV);

        float S[8][4];
        #pragma unroll
        for (int i = 0; i < 8; i++)
            #pragma unroll
            for (int j = 0; j < 4; j++) S[i][j] = 0.f;

        const uint32_t kAddr = base + kPat;
        #pragma unroll
        for (int nb = 0; nb < 4; nb++) {
            #pragma unroll
            for (int kb = 0; kb < 4; kb++) {
                uint32_t rh[4];
                ldsm4(rh, kAddr + A_KH + nb * (16 * AP) + kb * 32);
                mma_bf16(S[2 * nb], qh[kb], rh + 0);
                mma_bf16(S[2 * nb + 1], qh[kb], rh + 2);
                if (!fut) {
                    mma_bf16(S[2 * nb], ql[kb], rh + 0);
                    mma_bf16(S[2 * nb + 1], ql[kb], rh + 2);
                    uint32_t rl[4];
                    ldsm4(rl, kAddr + A_KL + nb * (16 * AP) + kb * 32);
                    mma_bf16(S[2 * nb], qh[kb], rl + 0);
                    mma_bf16(S[2 * nb + 1], qh[kb], rl + 2);
                }
            }
        }

        float rm0 = -1e30f, rm1 = -1e30f;
        #pragma unroll
        for (int i = 0; i < 8; i++) {
            rm0 = fmaxf(rm0, fmaxf(S[i][0], S[i][1]));
            rm1 = fmaxf(rm1, fmaxf(S[i][2], S[i][3]));
        }
        rm0 = fmaxf(rm0, __shfl_xor_sync(0xffffffffu, rm0, 1));
        rm0 = fmaxf(rm0, __shfl_xor_sync(0xffffffffu, rm0, 2));
        rm1 = fmaxf(rm1, __shfl_xor_sync(0xffffffffu, rm1, 1));
        rm1 = fmaxf(rm1, __shfl_xor_sync(0xffffffffu, rm1, 2));
        if (rm0 > m0 || rm1 > m1) {
            const float M0 = fmaxf(m0, rm0);
            const float M1 = fmaxf(m1, rm1);
            const float f0 = __expf(m0 - M0);
            const float f1 = __expf(m1 - M1);
            l0 *= f0; l1 *= f1;
            #pragma unroll
            for (int i = 0; i < 8; i++) {
                ctx[i][0] *= f0; ctx[i][1] *= f0;
                ctx[i][2] *= f1; ctx[i][3] *= f1;
            }
            m0 = M0; m1 = M1;
        }

        if (!fut) {
            uint32_t ph[8][2];
            const int jb = kt * 64 + 2 * tg;
            #pragma unroll
            for (int nt = 0; nt < 8; nt++) {
                const int j0 = jb + nt * 8;
                const float p0 = (j0 <= qg0) ? __expf(S[nt][0] - m0) : 0.f;
                const float p1 = (j0 + 1 <= qg0) ? __expf(S[nt][1] - m0) : 0.f;
                const float p2 = (j0 <= qg8) ? __expf(S[nt][2] - m1) : 0.f;
                const float p3 = (j0 + 1 <= qg8) ? __expf(S[nt][3] - m1) : 0.f;
                l0 += p0 + p1; l1 += p2 + p3;
                ph[nt][0] = packf_hi(p0, p1);
                ph[nt][1] = packf_hi(p2, p3);
            }
            // PV: 1-term (Ph.Vh)
            const uint32_t vAddr = base + vPat;
            #pragma unroll
            for (int kk = 0; kk < 4; kk++) {
                uint32_t Ahh[4] = { ph[2 * kk][0], ph[2 * kk][1],
                                    ph[2 * kk + 1][0], ph[2 * kk + 1][1] };
                #pragma unroll
                for (int db = 0; db < 4; db++) {
                    uint32_t vh4[4];
                    ldsm4t(vh4, vAddr + A_VH + kk * (16 * AP) + db * 32);
                    mma_bf16(ctx[2 * db], Ahh, vh4 + 0);
                    mma_bf16(ctx[2 * db + 1], Ahh, vh4 + 2);
                }
            }
        }
        stage = (stage + 1 == 3) ? 0 : stage + 1;
        pstage = (pstage + 1 == 3) ? 0 : pstage + 1;
    }

    l0 += __shfl_xor_sync(0xffffffffu, l0, 1);
    l0 += __shfl_xor_sync(0xffffffffu, l0, 2);
    l1 += __shfl_xor_sync(0xffffffffu, l1, 1);
    l1 += __shfl_xor_sync(0xffffffffu, l1, 2);
    const float inv0 = 1.0f / (l0 + EPSv);
    const float inv1 = 1.0f / (l1 + EPSv);

    const int b = bh >> 4, h = bh & 15;
    const size_t o0 = ((size_t)(b * Sv + qg0)) * Dv + h * 64;
    const size_t o8 = ((size_t)(b * Sv + qg8)) * Dv + h * 64;
    #pragma unroll
    for (int nt = 0; nt < 8; nt++) {
        const int d0 = nt * 8 + tg * 2;
        const float v0 = ctx[nt][0] * inv0, v1 = ctx[nt][1] * inv0;
        const float v2 = ctx[nt][2] * inv1, v3 = ctx[nt][3] * inv1;
        *(uint32_t*)(Chi + o0 + d0) = packf_hi(v0, v1);
        *(uint32_t*)(Clo + o0 + d0) = packf_lo(v0, v1);
        *(uint32_t*)(Chi + o8 + d0) = packf_hi(v2, v3);
        *(uint32_t*)(Clo + o8 + d0) = packf_lo(v2, v3);
    }
}

// ---------------- launch -----------------------------------------------------
extern "C" void kernel_launch(void* const* d_in, const int* in_sizes, int n_in,
                              void* d_out, int out_size)
{
    const float* x  = (const float*)d_in[0];
    const float* Wq = (const float*)d_in[1];
    const float* bq = (const float*)d_in[2];
    const float* Wk = (const float*)d_in[3];
    const float* bk = (const float*)d_in[4];
    const float* Wv = (const float*)d_in[5];
    const float* bv = (const float*)d_in[6];
    const float* Wo = (const float*)d_in[7];
    const float* bo = (const float*)d_in[8];
    float* out = (float*)d_out;

    __nv_bfloat16 *xhi, *xlo, *wh, *wl;
    __nv_bfloat16 *qhi, *qlo, *khi, *klo, *vhi, *vlo, *chi, *clo;
    cudaGetSymbolAddress((void**)&xhi, g_xhi);
    cudaGetSymbolAddress((void**)&xlo, g_xlo);
    cudaGetSymbolAddress((void**)&wh,  g_wh);
    cudaGetSymbolAddress((void**)&wl,  g_wl);
    cudaGetSymbolAddress((void**)&qhi, g_qhi);
    cudaGetSymbolAddress((void**)&qlo, g_qlo);
    cudaGetSymbolAddress((void**)&khi, g_khi);
    cudaGetSymbolAddress((void**)&klo, g_klo);
    cudaGetSymbolAddress((void**)&vhi, g_vhi);
    cudaGetSymbolAddress((void**)&vlo, g_vlo);
    cudaGetSymbolAddress((void**)&chi, g_chi);
    cudaGetSymbolAddress((void**)&clo, g_clo);

    cudaFuncSetAttribute(gemm_proj, cudaFuncAttributeMaxDynamicSharedMemorySize, SMEM_G);
    cudaFuncSetAttribute(gemm_out, cudaFuncAttributeMaxDynamicSharedMemorySize, SMEM_G);
    cudaFuncSetAttribute(attn_mma, cudaFuncAttributeMaxDynamicSharedMemorySize, SMEM_A);

    const int n4 = Mv * Dv / 4;
    split_rm<<<n4 / 256, 256>>>((const float4*)x, (__nv_bfloat162*)xhi,
                                (__nv_bfloat162*)xlo, n4);

    WSrc ws;
    ws.w[0] = Wq; ws.w[1] = Wk; ws.w[2] = Wv; ws.w[3] = Wo;
    dim3 tgrid(Dv / 32, Dv / 32, 4);
    tsplit4<<<tgrid, 256>>>(ws, wh, wl);

    ProjOut po;
    po.bias[0] = bq; po.bias[1] = bk; po.bias[2] = bv;
    po.oh[0] = qhi; po.oh[1] = khi; po.oh[2] = vhi;
    po.ol[0] = qlo; po.ol[1] = klo; po.ol[2] = vlo;

    dim3 pgrid(Dv / 128, Mv / 128, 3);   // fused Q/K/V
    gemm_proj<<<pgrid, 128, SMEM_G>>>(xhi, xlo, wh, wl, po);

    dim3 agrid(Sv / 128, Bv * Hv);       // (16, 64)
    attn_mma<<<agrid, 256, SMEM_A>>>(qhi, qlo, khi, klo, vhi, vlo, chi, clo);

    dim3 ggrid(Dv / 128, Mv / 128);
    gemm_out<<<ggrid, 128, SMEM_G>>>(chi, clo, wh + 3 * (size_t)Dv * Dv,
                                     wl + 3 * (size_t)Dv * Dv, bo, out);
}